// round 1
// baseline (speedup 1.0000x reference)
#include <cuda_runtime.h>

#define N_NODES 50000
#define N_EDGES 500000
#define DIM     512
#define NCLS    100

// Scratch (device globals — no allocation allowed in kernel_launch)
__device__ float g_h  [(size_t)N_NODES * DIM];   // GEMM output / scatter source
__device__ float g_agg[(size_t)N_NODES * DIM];   // aggregation target / next GEMM input
__device__ float g_norm[N_NODES];                // deg^{-1/2}

// ---------------------------------------------------------------------------
// degree / norm
// ---------------------------------------------------------------------------
__global__ void k_init_norm() {
    int i = blockIdx.x * blockDim.x + threadIdx.x;
    if (i < N_NODES) g_norm[i] = 1.0f;           // self-loop contributes 1
}

__global__ void k_count_deg(const int* __restrict__ ei) {
    int e = blockIdx.x * blockDim.x + threadIdx.x;
    if (e < N_EDGES) atomicAdd(&g_norm[ei[N_EDGES + e]], 1.0f);
}

__global__ void k_fin_norm() {
    int i = blockIdx.x * blockDim.x + threadIdx.x;
    if (i < N_NODES) g_norm[i] = rsqrtf(g_norm[i]);
}

// ---------------------------------------------------------------------------
// zero a float buffer (float4 granularity; count4 = #float4)
// ---------------------------------------------------------------------------
__global__ void k_zero4(float4* __restrict__ p, int count4) {
    int i = blockIdx.x * blockDim.x + threadIdx.x;
    if (i < count4) p[i] = make_float4(0.f, 0.f, 0.f, 0.f);
}

// ---------------------------------------------------------------------------
// edge scatter: agg[dst] += norm[src]*norm[dst] * h[src]
// one block (128 threads) per edge; each thread one float4 of the 512-dim row
// ---------------------------------------------------------------------------
__global__ void __launch_bounds__(128) k_scatter(const float* __restrict__ h,
                                                 float* __restrict__ agg,
                                                 const int* __restrict__ ei) {
    int e   = blockIdx.x;
    int src = ei[e];
    int dst = ei[N_EDGES + e];
    float coef = g_norm[src] * g_norm[dst];
    float4 v = reinterpret_cast<const float4*>(h + (size_t)src * DIM)[threadIdx.x];
    float* a = agg + (size_t)dst * DIM + threadIdx.x * 4;
    atomicAdd(a + 0, v.x * coef);
    atomicAdd(a + 1, v.y * coef);
    atomicAdd(a + 2, v.z * coef);
    atomicAdd(a + 3, v.w * coef);
}

// ---------------------------------------------------------------------------
// epilogue: agg = relu(agg + norm[v]^2 * h + bias)   (self-loop + bias + relu)
// ---------------------------------------------------------------------------
__global__ void k_epilogue(const float* __restrict__ h,
                           float* __restrict__ agg,
                           const float* __restrict__ bias) {
    int i4 = blockIdx.x * blockDim.x + threadIdx.x;
    const int TOTAL4 = N_NODES * (DIM / 4);
    if (i4 >= TOTAL4) return;
    int node = i4 / (DIM / 4);
    int f4   = i4 % (DIM / 4);
    float c = g_norm[node];
    c = c * c;
    float4 a = reinterpret_cast<float4*>(agg)[i4];
    float4 hh = reinterpret_cast<const float4*>(h)[i4];
    float4 b = reinterpret_cast<const float4*>(bias)[f4];
    float4 r;
    r.x = fmaxf(a.x + c * hh.x + b.x, 0.f);
    r.y = fmaxf(a.y + c * hh.y + b.y, 0.f);
    r.z = fmaxf(a.z + c * hh.z + b.z, 0.f);
    r.w = fmaxf(a.w + c * hh.w + b.w, 0.f);
    reinterpret_cast<float4*>(agg)[i4] = r;
}

// ---------------------------------------------------------------------------
// SGEMM: C[N,M] = A[N,K] * B[M,K]^T (+ optional bias over M)
// BM=BN=128, BK=16, 256 threads, 8x8 per-thread micro-tile.
// A and B are both row-major over K, so loads are symmetric.
// ---------------------------------------------------------------------------
#define BM 128
#define BN 128
#define BK 16

__global__ void __launch_bounds__(256) k_sgemm(const float* __restrict__ A,
                                               const float* __restrict__ B,
                                               float* __restrict__ C,
                                               const float* __restrict__ bias,
                                               int N, int M, int K) {
    __shared__ float As[BK][BM + 4];   // pad 4 keeps float4 alignment, breaks conflicts
    __shared__ float Bs[BK][BN + 4];

    const int t = threadIdx.x;
    const int ty = t >> 4;          // 0..15  (M direction)
    const int tx = t & 15;          // 0..15  (N direction)
    const int rowBase = blockIdx.y * BM;
    const int colBase = blockIdx.x * BN;

    float acc[8][8];
#pragma unroll
    for (int i = 0; i < 8; i++)
#pragma unroll
        for (int j = 0; j < 8; j++) acc[i][j] = 0.f;

    for (int k0 = 0; k0 < K; k0 += BK) {
        // each tile is 128 rows x 16 k = 512 float4; 256 threads x 2 float4
#pragma unroll
        for (int L = 0; L < 2; L++) {
            int id = t + L * 256;
            int r  = id >> 2;
            int kq = (id & 3) * 4;

            float4 va = make_float4(0.f, 0.f, 0.f, 0.f);
            int gr = rowBase + r;
            if (gr < N) va = *reinterpret_cast<const float4*>(A + (size_t)gr * K + k0 + kq);
            As[kq + 0][r] = va.x; As[kq + 1][r] = va.y;
            As[kq + 2][r] = va.z; As[kq + 3][r] = va.w;

            float4 vb = make_float4(0.f, 0.f, 0.f, 0.f);
            int gc = colBase + r;
            if (gc < M) vb = *reinterpret_cast<const float4*>(B + (size_t)gc * K + k0 + kq);
            Bs[kq + 0][r] = vb.x; Bs[kq + 1][r] = vb.y;
            Bs[kq + 2][r] = vb.z; Bs[kq + 3][r] = vb.w;
        }
        __syncthreads();

#pragma unroll
        for (int k = 0; k < BK; k++) {
            float4 a0 = *reinterpret_cast<const float4*>(&As[k][ty * 8]);
            float4 a1 = *reinterpret_cast<const float4*>(&As[k][ty * 8 + 4]);
            float4 b0 = *reinterpret_cast<const float4*>(&Bs[k][tx * 8]);
            float4 b1 = *reinterpret_cast<const float4*>(&Bs[k][tx * 8 + 4]);
            float a[8] = {a0.x, a0.y, a0.z, a0.w, a1.x, a1.y, a1.z, a1.w};
            float b[8] = {b0.x, b0.y, b0.z, b0.w, b1.x, b1.y, b1.z, b1.w};
#pragma unroll
            for (int i = 0; i < 8; i++)
#pragma unroll
                for (int j = 0; j < 8; j++) acc[i][j] = fmaf(a[i], b[j], acc[i][j]);
        }
        __syncthreads();
    }

#pragma unroll
    for (int i = 0; i < 8; i++) {
        int gr = rowBase + ty * 8 + i;
        if (gr >= N) continue;
#pragma unroll
        for (int j = 0; j < 8; j++) {
            int gc = colBase + tx * 8 + j;
            if (gc < M) {
                float v = acc[i][j];
                if (bias) v += bias[gc];
                C[(size_t)gr * M + gc] = v;
            }
        }
    }
}

// ---------------------------------------------------------------------------
// launch
// ---------------------------------------------------------------------------
extern "C" void kernel_launch(void* const* d_in, const int* in_sizes, int n_in,
                              void* d_out, int out_size) {
    const float* x  = (const float*)d_in[0];
    const int*   ei = (const int*)  d_in[1];
    const float* W1 = (const float*)d_in[2];
    const float* b1 = (const float*)d_in[3];
    const float* W2 = (const float*)d_in[4];
    const float* b2 = (const float*)d_in[5];
    const float* Wc = (const float*)d_in[6];
    const float* bc = (const float*)d_in[7];
    float* out = (float*)d_out;

    float *hP = nullptr, *aggP = nullptr;
    cudaGetSymbolAddress((void**)&hP,   g_h);
    cudaGetSymbolAddress((void**)&aggP, g_agg);

    const int TOTAL4 = N_NODES * (DIM / 4);

    // norm = rsqrt(1 + indeg)
    k_init_norm<<<(N_NODES + 255) / 256, 256>>>();
    k_count_deg<<<(N_EDGES + 255) / 256, 256>>>(ei);
    k_fin_norm <<<(N_NODES + 255) / 256, 256>>>();

    dim3 g1((DIM  + BN - 1) / BN, (N_NODES + BM - 1) / BM);   // (4, 391)
    dim3 g3((NCLS + BN - 1) / BN, (N_NODES + BM - 1) / BM);   // (1, 391)

    // ---- layer 1 ----
    k_sgemm<<<g1, 256>>>(x, W1, hP, nullptr, N_NODES, DIM, DIM);
    k_zero4<<<(TOTAL4 + 255) / 256, 256>>>((float4*)aggP, TOTAL4);
    k_scatter<<<N_EDGES, 128>>>(hP, aggP, ei);
    k_epilogue<<<(TOTAL4 + 255) / 256, 256>>>(hP, aggP, b1);

    // ---- layer 2 ----
    k_sgemm<<<g1, 256>>>(aggP, W2, hP, nullptr, N_NODES, DIM, DIM);
    k_zero4<<<(TOTAL4 + 255) / 256, 256>>>((float4*)aggP, TOTAL4);
    k_scatter<<<N_EDGES, 128>>>(hP, aggP, ei);
    k_epilogue<<<(TOTAL4 + 255) / 256, 256>>>(hP, aggP, b2);

    // ---- classifier ----
    k_sgemm<<<g3, 256>>>(aggP, Wc, out, bc, N_NODES, NCLS, DIM);
}

// round 2
// speedup vs baseline: 1.5579x; 1.5579x over previous
#include <cuda_runtime.h>

#define N_NODES 50000
#define N_EDGES 500000
#define DIM     512
#define NCLS    100

// Scratch (device globals — no allocation allowed)
__device__ float g_h  [(size_t)N_NODES * DIM];   // GEMM output / gather source
__device__ float g_agg[(size_t)N_NODES * DIM];   // gather target / next GEMM input
__device__ float g_norm[N_NODES];                // deg^{-1/2}
__device__ int   g_cnt [N_NODES];                // in-degree (excl. self loop)
__device__ int   g_fill[N_NODES];                // bucket fill cursors
__device__ int   g_off [N_NODES + 1];            // CSR row offsets (by dst)
__device__ int   g_csr_src [N_EDGES];            // CSR column indices (src)
__device__ float g_csr_coef[N_EDGES];            // norm[src]*norm[dst] per edge

// ---------------------------------------------------------------------------
// CSR build: count, norm, scan, fill
// ---------------------------------------------------------------------------
__global__ void k_zero_cnt() {
    int i = blockIdx.x * blockDim.x + threadIdx.x;
    if (i < N_NODES) { g_cnt[i] = 0; g_fill[i] = 0; }
}

__global__ void k_count(const int* __restrict__ ei) {
    int e = blockIdx.x * blockDim.x + threadIdx.x;
    if (e < N_EDGES) atomicAdd(&g_cnt[ei[N_EDGES + e]], 1);
}

__global__ void k_norm() {
    int i = blockIdx.x * blockDim.x + threadIdx.x;
    if (i < N_NODES) g_norm[i] = rsqrtf(1.0f + (float)g_cnt[i]);  // +1 self loop
}

// single-block inclusive scan over g_cnt -> exclusive offsets in g_off
__global__ void __launch_bounds__(1024) k_scan() {
    __shared__ int s[1024];
    __shared__ int carry;
    if (threadIdx.x == 0) carry = 0;
    __syncthreads();
    for (int base = 0; base < N_NODES; base += 1024) {
        int i = base + threadIdx.x;
        int v = (i < N_NODES) ? g_cnt[i] : 0;
        s[threadIdx.x] = v;
        __syncthreads();
#pragma unroll
        for (int off = 1; off < 1024; off <<= 1) {
            int t = (threadIdx.x >= off) ? s[threadIdx.x - off] : 0;
            __syncthreads();
            s[threadIdx.x] += t;
            __syncthreads();
        }
        if (i < N_NODES) g_off[i + 1] = s[threadIdx.x] + carry;
        __syncthreads();
        if (threadIdx.x == 0) carry += s[1023];
        __syncthreads();
    }
    if (threadIdx.x == 0) g_off[0] = 0;
}

__global__ void k_fill(const int* __restrict__ ei) {
    int e = blockIdx.x * blockDim.x + threadIdx.x;
    if (e >= N_EDGES) return;
    int src = ei[e];
    int dst = ei[N_EDGES + e];
    int pos = g_off[dst] + atomicAdd(&g_fill[dst], 1);
    g_csr_src [pos] = src;
    g_csr_coef[pos] = g_norm[src] * g_norm[dst];
}

// ---------------------------------------------------------------------------
// gather aggregation, fused self-loop + bias + relu:
//   agg[v] = relu( sum_{e->v} coef_e * h[src_e] + norm[v]^2 * h[v] + bias )
// one block (128 threads) per node, each thread owns one float4 of 512 dims
// ---------------------------------------------------------------------------
__global__ void __launch_bounds__(128) k_gather(const float* __restrict__ h,
                                                float* __restrict__ agg,
                                                const float* __restrict__ bias) {
    const int node = blockIdx.x;
    const int t    = threadIdx.x;
    const int beg  = g_off[node];
    const int end  = g_off[node + 1];

    float4 acc = make_float4(0.f, 0.f, 0.f, 0.f);
#pragma unroll 2
    for (int p = beg; p < end; p++) {
        int   src = g_csr_src[p];
        float c   = g_csr_coef[p];
        float4 v  = reinterpret_cast<const float4*>(h + (size_t)src * DIM)[t];
        acc.x = fmaf(c, v.x, acc.x);
        acc.y = fmaf(c, v.y, acc.y);
        acc.z = fmaf(c, v.z, acc.z);
        acc.w = fmaf(c, v.w, acc.w);
    }
    float cs = g_norm[node];
    cs = cs * cs;
    float4 hv = reinterpret_cast<const float4*>(h + (size_t)node * DIM)[t];
    float4 b  = reinterpret_cast<const float4*>(bias)[t];
    float4 r;
    r.x = fmaxf(fmaf(cs, hv.x, acc.x) + b.x, 0.f);
    r.y = fmaxf(fmaf(cs, hv.y, acc.y) + b.y, 0.f);
    r.z = fmaxf(fmaf(cs, hv.z, acc.z) + b.z, 0.f);
    r.w = fmaxf(fmaf(cs, hv.w, acc.w) + b.w, 0.f);
    reinterpret_cast<float4*>(agg + (size_t)node * DIM)[t] = r;
}

// ---------------------------------------------------------------------------
// SGEMM: C[N,M] = A[N,K] * B[M,K]^T (+ optional bias over M)  — unchanged R1
// ---------------------------------------------------------------------------
#define BM 128
#define BN 128
#define BK 16

__global__ void __launch_bounds__(256) k_sgemm(const float* __restrict__ A,
                                               const float* __restrict__ B,
                                               float* __restrict__ C,
                                               const float* __restrict__ bias,
                                               int N, int M, int K) {
    __shared__ float As[BK][BM + 4];
    __shared__ float Bs[BK][BN + 4];

    const int t = threadIdx.x;
    const int ty = t >> 4;
    const int tx = t & 15;
    const int rowBase = blockIdx.y * BM;
    const int colBase = blockIdx.x * BN;

    float acc[8][8];
#pragma unroll
    for (int i = 0; i < 8; i++)
#pragma unroll
        for (int j = 0; j < 8; j++) acc[i][j] = 0.f;

    for (int k0 = 0; k0 < K; k0 += BK) {
#pragma unroll
        for (int L = 0; L < 2; L++) {
            int id = t + L * 256;
            int r  = id >> 2;
            int kq = (id & 3) * 4;

            float4 va = make_float4(0.f, 0.f, 0.f, 0.f);
            int gr = rowBase + r;
            if (gr < N) va = *reinterpret_cast<const float4*>(A + (size_t)gr * K + k0 + kq);
            As[kq + 0][r] = va.x; As[kq + 1][r] = va.y;
            As[kq + 2][r] = va.z; As[kq + 3][r] = va.w;

            float4 vb = make_float4(0.f, 0.f, 0.f, 0.f);
            int gc = colBase + r;
            if (gc < M) vb = *reinterpret_cast<const float4*>(B + (size_t)gc * K + k0 + kq);
            Bs[kq + 0][r] = vb.x; Bs[kq + 1][r] = vb.y;
            Bs[kq + 2][r] = vb.z; Bs[kq + 3][r] = vb.w;
        }
        __syncthreads();

#pragma unroll
        for (int k = 0; k < BK; k++) {
            float4 a0 = *reinterpret_cast<const float4*>(&As[k][ty * 8]);
            float4 a1 = *reinterpret_cast<const float4*>(&As[k][ty * 8 + 4]);
            float4 b0 = *reinterpret_cast<const float4*>(&Bs[k][tx * 8]);
            float4 b1 = *reinterpret_cast<const float4*>(&Bs[k][tx * 8 + 4]);
            float a[8] = {a0.x, a0.y, a0.z, a0.w, a1.x, a1.y, a1.z, a1.w};
            float b[8] = {b0.x, b0.y, b0.z, b0.w, b1.x, b1.y, b1.z, b1.w};
#pragma unroll
            for (int i = 0; i < 8; i++)
#pragma unroll
                for (int j = 0; j < 8; j++) acc[i][j] = fmaf(a[i], b[j], acc[i][j]);
        }
        __syncthreads();
    }

#pragma unroll
    for (int i = 0; i < 8; i++) {
        int gr = rowBase + ty * 8 + i;
        if (gr >= N) continue;
#pragma unroll
        for (int j = 0; j < 8; j++) {
            int gc = colBase + tx * 8 + j;
            if (gc < M) {
                float v = acc[i][j];
                if (bias) v += bias[gc];
                C[(size_t)gr * M + gc] = v;
            }
        }
    }
}

// ---------------------------------------------------------------------------
// launch
// ---------------------------------------------------------------------------
extern "C" void kernel_launch(void* const* d_in, const int* in_sizes, int n_in,
                              void* d_out, int out_size) {
    const float* x  = (const float*)d_in[0];
    const int*   ei = (const int*)  d_in[1];
    const float* W1 = (const float*)d_in[2];
    const float* b1 = (const float*)d_in[3];
    const float* W2 = (const float*)d_in[4];
    const float* b2 = (const float*)d_in[5];
    const float* Wc = (const float*)d_in[6];
    const float* bc = (const float*)d_in[7];
    float* out = (float*)d_out;

    float *hP = nullptr, *aggP = nullptr;
    cudaGetSymbolAddress((void**)&hP,   g_h);
    cudaGetSymbolAddress((void**)&aggP, g_agg);

    // ---- CSR build (by dst) + norms ----
    k_zero_cnt<<<(N_NODES + 255) / 256, 256>>>();
    k_count   <<<(N_EDGES + 255) / 256, 256>>>(ei);
    k_norm    <<<(N_NODES + 255) / 256, 256>>>();
    k_scan    <<<1, 1024>>>();
    k_fill    <<<(N_EDGES + 255) / 256, 256>>>(ei);

    dim3 g1((DIM  + BN - 1) / BN, (N_NODES + BM - 1) / BM);
    dim3 g3((NCLS + BN - 1) / BN, (N_NODES + BM - 1) / BM);

    // ---- layer 1 ----
    k_sgemm <<<g1, 256>>>(x, W1, hP, nullptr, N_NODES, DIM, DIM);
    k_gather<<<N_NODES, 128>>>(hP, aggP, b1);

    // ---- layer 2 ----
    k_sgemm <<<g1, 256>>>(aggP, W2, hP, nullptr, N_NODES, DIM, DIM);
    k_gather<<<N_NODES, 128>>>(hP, aggP, b2);

    // ---- classifier ----
    k_sgemm<<<g3, 256>>>(aggP, Wc, out, bc, N_NODES, NCLS, DIM);
}

// round 3
// speedup vs baseline: 2.1426x; 1.3753x over previous
#include <cuda_runtime.h>
#include <cuda_bf16.h>

#define N_NODES 50000
#define N_EDGES 500000
#define DIM     512
#define NCLS    100
#define KP      1536          // split-K: [hi|lo|hi] x [hi|hi|lo]

// ---------------------------------------------------------------------------
// scratch (device globals)
// ---------------------------------------------------------------------------
__device__ float g_h  [(size_t)N_NODES * DIM];
__device__ float g_agg[(size_t)N_NODES * DIM];
__device__ float g_norm[N_NODES];
__device__ int   g_cnt [N_NODES];
__device__ int   g_fill[N_NODES];
__device__ int   g_off [N_NODES + 1];
__device__ int   g_csr_src [N_EDGES];
__device__ float g_csr_coef[N_EDGES];
__device__ __nv_bfloat16 g_a16 [(size_t)N_NODES * KP];  // split node features
__device__ __nv_bfloat16 g_w16a[(size_t)DIM * KP];      // split W1
__device__ __nv_bfloat16 g_w16b[(size_t)DIM * KP];      // split W2
__device__ __nv_bfloat16 g_wc16[(size_t)NCLS * KP];     // split Wc

// ---------------------------------------------------------------------------
// CSR build
// ---------------------------------------------------------------------------
__global__ void k_zero_cnt() {
    int i = blockIdx.x * blockDim.x + threadIdx.x;
    if (i < N_NODES) { g_cnt[i] = 0; g_fill[i] = 0; }
}

__global__ void k_count(const int* __restrict__ ei) {
    int e = blockIdx.x * blockDim.x + threadIdx.x;
    if (e < N_EDGES) atomicAdd(&g_cnt[ei[N_EDGES + e]], 1);
}

__global__ void k_norm() {
    int i = blockIdx.x * blockDim.x + threadIdx.x;
    if (i < N_NODES) g_norm[i] = rsqrtf(1.0f + (float)g_cnt[i]);
}

// one-block scan: serial-per-thread + warp shuffle block scan
__global__ void __launch_bounds__(1024) k_scan() {
    __shared__ int wsum[32];
    const int t  = threadIdx.x;
    const int CH = 49;                       // 1024*49 >= 50000
    const int base = t * CH;
    int s = 0;
    for (int i = 0; i < CH; i++) {
        int idx = base + i;
        if (idx < N_NODES) s += g_cnt[idx];
    }
    int incl = s;
#pragma unroll
    for (int o = 1; o < 32; o <<= 1) {
        int v = __shfl_up_sync(0xffffffffu, incl, o);
        if ((t & 31) >= o) incl += v;
    }
    if ((t & 31) == 31) wsum[t >> 5] = incl;
    __syncthreads();
    if (t < 32) {
        int v = wsum[t];
        int iv = v;
#pragma unroll
        for (int o = 1; o < 32; o <<= 1) {
            int u = __shfl_up_sync(0xffffffffu, iv, o);
            if (t >= o) iv += u;
        }
        wsum[t] = iv - v;                    // exclusive warp prefix
    }
    __syncthreads();
    int acc = incl - s + wsum[t >> 5];       // exclusive prefix for this thread
    for (int i = 0; i < CH; i++) {
        int idx = base + i;
        if (idx < N_NODES) {
            acc += g_cnt[idx];
            g_off[idx + 1] = acc;
        }
    }
    if (t == 0) g_off[0] = 0;
}

__global__ void k_fill(const int* __restrict__ ei) {
    int e = blockIdx.x * blockDim.x + threadIdx.x;
    if (e >= N_EDGES) return;
    int src = ei[e];
    int dst = ei[N_EDGES + e];
    int pos = g_off[dst] + atomicAdd(&g_fill[dst], 1);
    g_csr_src [pos] = src;
    g_csr_coef[pos] = g_norm[src] * g_norm[dst];
}

// ---------------------------------------------------------------------------
// fp32 -> split bf16 conversion
// feat rows: [hi | lo | hi] ; weight rows: [hi | hi | lo]
// process 2 floats per thread (one bf16x2 per segment write)
// ---------------------------------------------------------------------------
__device__ __forceinline__ void split2(float2 a, unsigned& hi2, unsigned& lo2) {
    __nv_bfloat16 hx = __float2bfloat16(a.x);
    __nv_bfloat16 hy = __float2bfloat16(a.y);
    __nv_bfloat16 lx = __float2bfloat16(a.x - __bfloat162float(hx));
    __nv_bfloat16 ly = __float2bfloat16(a.y - __bfloat162float(hy));
    __nv_bfloat162 h = __halves2bfloat162(hx, hy);
    __nv_bfloat162 l = __halves2bfloat162(lx, ly);
    hi2 = *reinterpret_cast<unsigned*>(&h);
    lo2 = *reinterpret_cast<unsigned*>(&l);
}

__global__ void k_split_feat(const float* __restrict__ src,
                             __nv_bfloat16* __restrict__ dst, int n) {
    int i2 = blockIdx.x * blockDim.x + threadIdx.x;      // pair index
    int total2 = n * (DIM / 2);
    if (i2 >= total2) return;
    int row = i2 / (DIM / 2);
    int k2  = i2 % (DIM / 2);
    float2 a = reinterpret_cast<const float2*>(src)[i2];
    unsigned hi2, lo2;
    split2(a, hi2, lo2);
    unsigned* d = reinterpret_cast<unsigned*>(dst + (size_t)row * KP) + k2;
    d[0]                 = hi2;   // [0:512)   hi
    d[DIM / 2]           = lo2;   // [512:1024) lo
    d[DIM]               = hi2;   // [1024:1536) hi
}

__global__ void k_split_w(const float* __restrict__ src,
                          __nv_bfloat16* __restrict__ dst, int n) {
    int i2 = blockIdx.x * blockDim.x + threadIdx.x;
    int total2 = n * (DIM / 2);
    if (i2 >= total2) return;
    int row = i2 / (DIM / 2);
    int k2  = i2 % (DIM / 2);
    float2 a = reinterpret_cast<const float2*>(src)[i2];
    unsigned hi2, lo2;
    split2(a, hi2, lo2);
    unsigned* d = reinterpret_cast<unsigned*>(dst + (size_t)row * KP) + k2;
    d[0]       = hi2;   // hi
    d[DIM / 2] = hi2;   // hi
    d[DIM]     = lo2;   // lo
}

// ---------------------------------------------------------------------------
// gather aggregation (unchanged from R2)
// ---------------------------------------------------------------------------
__global__ void __launch_bounds__(128) k_gather(const float* __restrict__ h,
                                                float* __restrict__ agg,
                                                const float* __restrict__ bias) {
    const int node = blockIdx.x;
    const int t    = threadIdx.x;
    const int beg  = g_off[node];
    const int end  = g_off[node + 1];

    float4 acc = make_float4(0.f, 0.f, 0.f, 0.f);
#pragma unroll 2
    for (int p = beg; p < end; p++) {
        int   src = g_csr_src[p];
        float c   = g_csr_coef[p];
        float4 v  = reinterpret_cast<const float4*>(h + (size_t)src * DIM)[t];
        acc.x = fmaf(c, v.x, acc.x);
        acc.y = fmaf(c, v.y, acc.y);
        acc.z = fmaf(c, v.z, acc.z);
        acc.w = fmaf(c, v.w, acc.w);
    }
    float cs = g_norm[node];
    cs = cs * cs;
    float4 hv = reinterpret_cast<const float4*>(h + (size_t)node * DIM)[t];
    float4 b  = reinterpret_cast<const float4*>(bias)[t];
    float4 r;
    r.x = fmaxf(fmaf(cs, hv.x, acc.x) + b.x, 0.f);
    r.y = fmaxf(fmaf(cs, hv.y, acc.y) + b.y, 0.f);
    r.z = fmaxf(fmaf(cs, hv.z, acc.z) + b.z, 0.f);
    r.w = fmaxf(fmaf(cs, hv.w, acc.w) + b.w, 0.f);
    reinterpret_cast<float4*>(agg + (size_t)node * DIM)[t] = r;
}

// ---------------------------------------------------------------------------
// bf16 tensor-core GEMM: C[N,M] = A'[N,KP] * B'[M,KP]^T (+bias)
// block 128x128, BK=32, 256 threads (8 warps, 4x2), warp tile 32x64
// mma.sync m16n8k16 bf16, ldmatrix.x4 fragment loads
// ---------------------------------------------------------------------------
#define GBM 128
#define GBN 128
#define GBK 32
#define APITCH 40   // bf16 elements per SMEM row (80B: conflict-free ldmatrix)

__device__ __forceinline__ void mma_bf16(float* d, const unsigned* a,
                                         unsigned b0, unsigned b1) {
    asm volatile(
        "mma.sync.aligned.m16n8k16.row.col.f32.bf16.bf16.f32 "
        "{%0,%1,%2,%3}, {%4,%5,%6,%7}, {%8,%9}, {%0,%1,%2,%3};"
        : "+f"(d[0]), "+f"(d[1]), "+f"(d[2]), "+f"(d[3])
        : "r"(a[0]), "r"(a[1]), "r"(a[2]), "r"(a[3]), "r"(b0), "r"(b1));
}

__device__ __forceinline__ void ldmx4(unsigned* r, unsigned addr) {
    asm volatile(
        "ldmatrix.sync.aligned.m8n8.x4.shared.b16 {%0,%1,%2,%3}, [%4];"
        : "=r"(r[0]), "=r"(r[1]), "=r"(r[2]), "=r"(r[3])
        : "r"(addr));
}

__global__ void __launch_bounds__(256) k_gemm_bf16(const __nv_bfloat16* __restrict__ A,
                                                   const __nv_bfloat16* __restrict__ B,
                                                   float* __restrict__ C,
                                                   const float* __restrict__ bias,
                                                   int N, int M) {
    __shared__ __nv_bfloat16 As[GBM * APITCH];
    __shared__ __nv_bfloat16 Bs[GBN * APITCH];

    const int t    = threadIdx.x;
    const int lane = t & 31;
    const int warp = t >> 5;
    const int wm   = warp & 3;          // 0..3 -> 32-row slab
    const int wn   = warp >> 2;         // 0..1 -> 64-col slab
    const int rowBase = blockIdx.y * GBM;
    const int colBase = blockIdx.x * GBN;

    const unsigned asBase = (unsigned)__cvta_generic_to_shared(As);
    const unsigned bsBase = (unsigned)__cvta_generic_to_shared(Bs);

    const int lg = lane >> 3;           // ldmatrix tile group 0..3
    const int lr = lane & 7;            // row within 8x8 tile

    float acc[2][8][4];
#pragma unroll
    for (int i = 0; i < 2; i++)
#pragma unroll
        for (int j = 0; j < 8; j++)
#pragma unroll
            for (int q = 0; q < 4; q++) acc[i][j][q] = 0.f;

    for (int k0 = 0; k0 < KP; k0 += GBK) {
        // load 128x32 bf16 tiles: 512 chunks of 16B each, 2 per thread
#pragma unroll
        for (int L = 0; L < 2; L++) {
            int chunk = t + L * 256;
            int r = chunk >> 2;
            int c = chunk & 3;          // 16B sub-chunk (8 bf16)
            uint4 va = make_uint4(0, 0, 0, 0);
            int gr = rowBase + r;
            if (gr < N) va = *reinterpret_cast<const uint4*>(A + (size_t)gr * KP + k0 + c * 8);
            *reinterpret_cast<uint4*>(As + r * APITCH + c * 8) = va;
            uint4 vb = make_uint4(0, 0, 0, 0);
            int gc = colBase + r;
            if (gc < M) vb = *reinterpret_cast<const uint4*>(B + (size_t)gc * KP + k0 + c * 8);
            *reinterpret_cast<uint4*>(Bs + r * APITCH + c * 8) = vb;
        }
        __syncthreads();

#pragma unroll
        for (int kk = 0; kk < GBK; kk += 16) {
            unsigned a[2][4];
#pragma unroll
            for (int mt = 0; mt < 2; mt++) {
                int row = wm * 32 + mt * 16 + (lg & 1) * 8 + lr;
                int kel = kk + (lg >> 1) * 8;
                ldmx4(a[mt], asBase + (unsigned)((row * APITCH + kel) * 2));
            }
            unsigned b[4][4];
#pragma unroll
            for (int nq = 0; nq < 4; nq++) {
                int nrow = wn * 64 + nq * 16 + (lg >> 1) * 8 + lr;
                int kel  = kk + (lg & 1) * 8;
                ldmx4(b[nq], bsBase + (unsigned)((nrow * APITCH + kel) * 2));
            }
#pragma unroll
            for (int mt = 0; mt < 2; mt++)
#pragma unroll
                for (int nt = 0; nt < 8; nt++) {
                    int nq = nt >> 1;
                    int h  = (nt & 1) * 2;
                    mma_bf16(acc[mt][nt], a[mt], b[nq][h], b[nq][h + 1]);
                }
        }
        __syncthreads();
    }

    // epilogue
    const int group = lane >> 2;
    const int qt    = lane & 3;
#pragma unroll
    for (int mt = 0; mt < 2; mt++) {
#pragma unroll
        for (int nt = 0; nt < 8; nt++) {
            int row0 = rowBase + wm * 32 + mt * 16 + group;
            int col  = colBase + wn * 64 + nt * 8 + qt * 2;
            float b0v = 0.f, b1v = 0.f;
            if (bias) {
                if (col < M)     b0v = bias[col];
                if (col + 1 < M) b1v = bias[col + 1];
            }
            if (row0 < N) {
                if (col + 1 < M) {
                    float2 v = make_float2(acc[mt][nt][0] + b0v, acc[mt][nt][1] + b1v);
                    *reinterpret_cast<float2*>(C + (size_t)row0 * M + col) = v;
                } else if (col < M) {
                    C[(size_t)row0 * M + col] = acc[mt][nt][0] + b0v;
                }
            }
            int row1 = row0 + 8;
            if (row1 < N) {
                if (col + 1 < M) {
                    float2 v = make_float2(acc[mt][nt][2] + b0v, acc[mt][nt][3] + b1v);
                    *reinterpret_cast<float2*>(C + (size_t)row1 * M + col) = v;
                } else if (col < M) {
                    C[(size_t)row1 * M + col] = acc[mt][nt][2] + b0v;
                }
            }
        }
    }
}

// ---------------------------------------------------------------------------
// launch
// ---------------------------------------------------------------------------
extern "C" void kernel_launch(void* const* d_in, const int* in_sizes, int n_in,
                              void* d_out, int out_size) {
    const float* x  = (const float*)d_in[0];
    const int*   ei = (const int*)  d_in[1];
    const float* W1 = (const float*)d_in[2];
    const float* b1 = (const float*)d_in[3];
    const float* W2 = (const float*)d_in[4];
    const float* b2 = (const float*)d_in[5];
    const float* Wc = (const float*)d_in[6];
    const float* bc = (const float*)d_in[7];
    float* out = (float*)d_out;

    float *hP = nullptr, *aggP = nullptr;
    __nv_bfloat16 *a16 = nullptr, *w16a = nullptr, *w16b = nullptr, *wc16 = nullptr;
    cudaGetSymbolAddress((void**)&hP,   g_h);
    cudaGetSymbolAddress((void**)&aggP, g_agg);
    cudaGetSymbolAddress((void**)&a16,  g_a16);
    cudaGetSymbolAddress((void**)&w16a, g_w16a);
    cudaGetSymbolAddress((void**)&w16b, g_w16b);
    cudaGetSymbolAddress((void**)&wc16, g_wc16);

    // ---- CSR build + norms ----
    k_zero_cnt<<<(N_NODES + 255) / 256, 256>>>();
    k_count   <<<(N_EDGES + 255) / 256, 256>>>(ei);
    k_norm    <<<(N_NODES + 255) / 256, 256>>>();
    k_scan    <<<1, 1024>>>();
    k_fill    <<<(N_EDGES + 255) / 256, 256>>>(ei);

    // ---- weight splits (once) ----
    const int WT2 = DIM * (DIM / 2);
    k_split_w<<<(WT2 + 255) / 256, 256>>>(W1, w16a, DIM);
    k_split_w<<<(WT2 + 255) / 256, 256>>>(W2, w16b, DIM);
    const int WC2 = NCLS * (DIM / 2);
    k_split_w<<<(WC2 + 255) / 256, 256>>>(Wc, wc16, NCLS);

    const int FT2 = N_NODES * (DIM / 2);
    dim3 g1((DIM  + GBN - 1) / GBN, (N_NODES + GBM - 1) / GBM);   // (4, 391)
    dim3 g3((NCLS + GBN - 1) / GBN, (N_NODES + GBM - 1) / GBM);   // (1, 391)

    // ---- layer 1 ----
    k_split_feat<<<(FT2 + 255) / 256, 256>>>(x, a16, N_NODES);
    k_gemm_bf16 <<<g1, 256>>>(a16, w16a, hP, nullptr, N_NODES, DIM);
    k_gather    <<<N_NODES, 128>>>(hP, aggP, b1);

    // ---- layer 2 ----
    k_split_feat<<<(FT2 + 255) / 256, 256>>>(aggP, a16, N_NODES);
    k_gemm_bf16 <<<g1, 256>>>(a16, w16b, hP, nullptr, N_NODES, DIM);
    k_gather    <<<N_NODES, 128>>>(hP, aggP, b2);

    // ---- classifier ----
    k_split_feat<<<(FT2 + 255) / 256, 256>>>(aggP, a16, N_NODES);
    k_gemm_bf16 <<<g3, 256>>>(a16, wc16, out, bc, N_NODES, NCLS);
}

// round 4
// speedup vs baseline: 2.5238x; 1.1779x over previous
#include <cuda_runtime.h>
#include <cuda_bf16.h>

#define N_NODES 50000
#define N_EDGES 500000
#define DIM     512
#define NCLS    100

// ---------------------------------------------------------------------------
// scratch (device globals)
// ---------------------------------------------------------------------------
__device__ float g_h  [(size_t)N_NODES * DIM];
__device__ float g_agg[(size_t)N_NODES * DIM];
__device__ float g_norm[N_NODES];
__device__ int   g_cnt [N_NODES];
__device__ int   g_fill[N_NODES];
__device__ int   g_off [N_NODES + 1];
__device__ int   g_csr_src [N_EDGES];
__device__ float g_csr_coef[N_EDGES];

__device__ __nv_bfloat16 g_w1hi[(size_t)DIM * DIM];
__device__ __nv_bfloat16 g_w1lo[(size_t)DIM * DIM];
__device__ __nv_bfloat16 g_w2hi[(size_t)DIM * DIM];
__device__ __nv_bfloat16 g_w2lo[(size_t)DIM * DIM];
__device__ __nv_bfloat16 g_wchi[(size_t)NCLS * DIM];
__device__ __nv_bfloat16 g_wclo[(size_t)NCLS * DIM];

#define SCAN_BLOCKS 196  // 196*256 = 50176 >= 50000
__device__ int g_bsum[SCAN_BLOCKS];
__device__ int g_bpre[SCAN_BLOCKS];

// ---------------------------------------------------------------------------
// CSR build
// ---------------------------------------------------------------------------
__global__ void k_zero_cnt() {
    int i = blockIdx.x * blockDim.x + threadIdx.x;
    if (i < N_NODES) { g_cnt[i] = 0; g_fill[i] = 0; }
}

__global__ void k_count(const int* __restrict__ ei) {
    int e = blockIdx.x * blockDim.x + threadIdx.x;
    if (e < N_EDGES) atomicAdd(&g_cnt[ei[N_EDGES + e]], 1);
}

__global__ void k_norm() {
    int i = blockIdx.x * blockDim.x + threadIdx.x;
    if (i < N_NODES) g_norm[i] = rsqrtf(1.0f + (float)g_cnt[i]);
}

// inclusive block scan of 256 ints via shuffles; returns inclusive prefix,
// and writes block total to *tot (thread 255's value)
__device__ __forceinline__ int block_scan256(int v, int t, int* sh, int* tot) {
    int incl = v;
#pragma unroll
    for (int o = 1; o < 32; o <<= 1) {
        int u = __shfl_up_sync(0xffffffffu, incl, o);
        if ((t & 31) >= o) incl += u;
    }
    if ((t & 31) == 31) sh[t >> 5] = incl;
    __syncthreads();
    if (t < 8) {
        int w = sh[t];
        int iw = w;
#pragma unroll
        for (int o = 1; o < 8; o <<= 1) {
            int u = __shfl_up_sync(0xffu, iw, o);
            if (t >= o) iw += u;
        }
        sh[t] = iw - w;              // exclusive warp prefix
        if (t == 7) *tot = iw;       // total
    }
    __syncthreads();
    return incl + sh[t >> 5];
}

__global__ void __launch_bounds__(256) k_scan1() {
    __shared__ int sh[8]; __shared__ int tot;
    int i = blockIdx.x * 256 + threadIdx.x;
    int v = (i < N_NODES) ? g_cnt[i] : 0;
    block_scan256(v, threadIdx.x, sh, &tot);
    __syncthreads();
    if (threadIdx.x == 0) g_bsum[blockIdx.x] = tot;
}

__global__ void __launch_bounds__(256) k_scan2() {
    __shared__ int sh[8]; __shared__ int tot;
    int t = threadIdx.x;
    int v = (t < SCAN_BLOCKS) ? g_bsum[t] : 0;
    int incl = block_scan256(v, t, sh, &tot);
    if (t < SCAN_BLOCKS) g_bpre[t] = incl - v;   // exclusive
}

__global__ void __launch_bounds__(256) k_scan3() {
    __shared__ int sh[8]; __shared__ int tot;
    int i = blockIdx.x * 256 + threadIdx.x;
    int v = (i < N_NODES) ? g_cnt[i] : 0;
    int incl = block_scan256(v, threadIdx.x, sh, &tot);
    if (i < N_NODES) g_off[i + 1] = incl + g_bpre[blockIdx.x];
    if (i == 0) g_off[0] = 0;
}

__global__ void k_fill(const int* __restrict__ ei) {
    int e = blockIdx.x * blockDim.x + threadIdx.x;
    if (e >= N_EDGES) return;
    int src = ei[e];
    int dst = ei[N_EDGES + e];
    int pos = g_off[dst] + atomicAdd(&g_fill[dst], 1);
    g_csr_src [pos] = src;
    g_csr_coef[pos] = g_norm[src] * g_norm[dst];
}

// ---------------------------------------------------------------------------
// weight split: W -> (hi, lo) bf16 arrays, row-major over K=512
// ---------------------------------------------------------------------------
__device__ __forceinline__ void split2(float2 a, unsigned& hi2, unsigned& lo2) {
    __nv_bfloat16 hx = __float2bfloat16(a.x);
    __nv_bfloat16 hy = __float2bfloat16(a.y);
    __nv_bfloat16 lx = __float2bfloat16(a.x - __bfloat162float(hx));
    __nv_bfloat16 ly = __float2bfloat16(a.y - __bfloat162float(hy));
    __nv_bfloat162 h = __halves2bfloat162(hx, hy);
    __nv_bfloat162 l = __halves2bfloat162(lx, ly);
    hi2 = *reinterpret_cast<unsigned*>(&h);
    lo2 = *reinterpret_cast<unsigned*>(&l);
}

__global__ void k_split_w(const float* __restrict__ src,
                          __nv_bfloat16* __restrict__ whi,
                          __nv_bfloat16* __restrict__ wlo, int n) {
    int i2 = blockIdx.x * blockDim.x + threadIdx.x;
    int total2 = n * (DIM / 2);
    if (i2 >= total2) return;
    float2 a = reinterpret_cast<const float2*>(src)[i2];
    unsigned hi2, lo2;
    split2(a, hi2, lo2);
    reinterpret_cast<unsigned*>(whi)[i2] = hi2;
    reinterpret_cast<unsigned*>(wlo)[i2] = lo2;
}

// ---------------------------------------------------------------------------
// gather aggregation (fused self-loop + bias + relu)
// ---------------------------------------------------------------------------
__global__ void __launch_bounds__(128) k_gather(const float* __restrict__ h,
                                                float* __restrict__ agg,
                                                const float* __restrict__ bias) {
    const int node = blockIdx.x;
    const int t    = threadIdx.x;
    const int beg  = g_off[node];
    const int end  = g_off[node + 1];

    float4 acc = make_float4(0.f, 0.f, 0.f, 0.f);
#pragma unroll 2
    for (int p = beg; p < end; p++) {
        int   src = g_csr_src[p];
        float c   = g_csr_coef[p];
        float4 v  = reinterpret_cast<const float4*>(h + (size_t)src * DIM)[t];
        acc.x = fmaf(c, v.x, acc.x);
        acc.y = fmaf(c, v.y, acc.y);
        acc.z = fmaf(c, v.z, acc.z);
        acc.w = fmaf(c, v.w, acc.w);
    }
    float cs = g_norm[node];
    cs = cs * cs;
    float4 hv = reinterpret_cast<const float4*>(h + (size_t)node * DIM)[t];
    float4 b  = reinterpret_cast<const float4*>(bias)[t];
    float4 r;
    r.x = fmaxf(fmaf(cs, hv.x, acc.x) + b.x, 0.f);
    r.y = fmaxf(fmaf(cs, hv.y, acc.y) + b.y, 0.f);
    r.z = fmaxf(fmaf(cs, hv.z, acc.z) + b.z, 0.f);
    r.w = fmaxf(fmaf(cs, hv.w, acc.w) + b.w, 0.f);
    reinterpret_cast<float4*>(agg + (size_t)node * DIM)[t] = r;
}

// ---------------------------------------------------------------------------
// fused split + bf16 tensor-core GEMM:
//   C[N,M] = A[N,512](fp32) * W[M,512]^T (+bias), via
//   Ahi*Whi + Alo*Whi + Ahi*Wlo  (all bf16 mma, fp32 accum)
// block 128x128, K-chunk 32, 256 threads (8 warps 4x2), warp tile 32x64
// ---------------------------------------------------------------------------
#define GBM 128
#define GBN 128
#define GBK 32
#define APITCH 40   // bf16 elems per SMEM row; 80B pitch -> conflict-free ldmatrix

__device__ __forceinline__ void mma_bf16(float* d, const unsigned* a,
                                         unsigned b0, unsigned b1) {
    asm volatile(
        "mma.sync.aligned.m16n8k16.row.col.f32.bf16.bf16.f32 "
        "{%0,%1,%2,%3}, {%4,%5,%6,%7}, {%8,%9}, {%0,%1,%2,%3};"
        : "+f"(d[0]), "+f"(d[1]), "+f"(d[2]), "+f"(d[3])
        : "r"(a[0]), "r"(a[1]), "r"(a[2]), "r"(a[3]), "r"(b0), "r"(b1));
}

__device__ __forceinline__ void ldmx4(unsigned* r, unsigned addr) {
    asm volatile(
        "ldmatrix.sync.aligned.m8n8.x4.shared.b16 {%0,%1,%2,%3}, [%4];"
        : "=r"(r[0]), "=r"(r[1]), "=r"(r[2]), "=r"(r[3])
        : "r"(addr));
}

__global__ void __launch_bounds__(256) k_gemm_fused(const float* __restrict__ A,
                                                    const __nv_bfloat16* __restrict__ Whi,
                                                    const __nv_bfloat16* __restrict__ Wlo,
                                                    float* __restrict__ C,
                                                    const float* __restrict__ bias,
                                                    int N, int M) {
    __shared__ __nv_bfloat16 Ah[GBM * APITCH];
    __shared__ __nv_bfloat16 Al[GBM * APITCH];
    __shared__ __nv_bfloat16 Bh[GBN * APITCH];
    __shared__ __nv_bfloat16 Bl[GBN * APITCH];

    const int t    = threadIdx.x;
    const int lane = t & 31;
    const int warp = t >> 5;
    const int wm   = warp & 3;
    const int wn   = warp >> 2;
    const int rowBase = blockIdx.y * GBM;
    const int colBase = blockIdx.x * GBN;

    const unsigned ahB = (unsigned)__cvta_generic_to_shared(Ah);
    const unsigned alB = (unsigned)__cvta_generic_to_shared(Al);
    const unsigned bhB = (unsigned)__cvta_generic_to_shared(Bh);
    const unsigned blB = (unsigned)__cvta_generic_to_shared(Bl);

    const int lg = lane >> 3;
    const int lr = lane & 7;

    float acc[2][8][4];
#pragma unroll
    for (int i = 0; i < 2; i++)
#pragma unroll
        for (int j = 0; j < 8; j++)
#pragma unroll
            for (int q = 0; q < 4; q++) acc[i][j][q] = 0.f;

    for (int k0 = 0; k0 < DIM; k0 += GBK) {
        // --- stage A (fp32 -> hi/lo bf16): 128 rows x 32 floats = 1024 float4
#pragma unroll
        for (int L = 0; L < 4; L++) {
            int chunk = t + L * 256;
            int r = chunk >> 3;          // 8 float4 per row
            int c = chunk & 7;           // float4 index within 32 floats
            float4 v = make_float4(0.f, 0.f, 0.f, 0.f);
            int gr = rowBase + r;
            if (gr < N) v = *reinterpret_cast<const float4*>(A + (size_t)gr * DIM + k0 + c * 4);
            unsigned h0, l0, h1, l1;
            split2(make_float2(v.x, v.y), h0, l0);
            split2(make_float2(v.z, v.w), h1, l1);
            *reinterpret_cast<uint2*>(Ah + r * APITCH + c * 4) = make_uint2(h0, h1);
            *reinterpret_cast<uint2*>(Al + r * APITCH + c * 4) = make_uint2(l0, l1);
        }
        // --- stage B (pre-split bf16): 128 rows x 32 bf16 per array = 512 uint4
#pragma unroll
        for (int L = 0; L < 2; L++) {
            int chunk = t + L * 256;
            int r = chunk >> 2;
            int c = chunk & 3;           // 16B sub-chunk (8 bf16)
            uint4 vh = make_uint4(0, 0, 0, 0);
            uint4 vl = make_uint4(0, 0, 0, 0);
            int gc = colBase + r;
            if (gc < M) {
                vh = *reinterpret_cast<const uint4*>(Whi + (size_t)gc * DIM + k0 + c * 8);
                vl = *reinterpret_cast<const uint4*>(Wlo + (size_t)gc * DIM + k0 + c * 8);
            }
            *reinterpret_cast<uint4*>(Bh + r * APITCH + c * 8) = vh;
            *reinterpret_cast<uint4*>(Bl + r * APITCH + c * 8) = vl;
        }
        __syncthreads();

#pragma unroll
        for (int kk = 0; kk < GBK; kk += 16) {
            unsigned ah[2][4], al[2][4];
#pragma unroll
            for (int mt = 0; mt < 2; mt++) {
                int row = wm * 32 + mt * 16 + (lg & 1) * 8 + lr;
                int kel = kk + (lg >> 1) * 8;
                unsigned off = (unsigned)((row * APITCH + kel) * 2);
                ldmx4(ah[mt], ahB + off);
                ldmx4(al[mt], alB + off);
            }
            unsigned b[4][4];
            // pass 1+2: b = Whi ; acc += Ahi*Whi + Alo*Whi
#pragma unroll
            for (int nq = 0; nq < 4; nq++) {
                int nrow = wn * 64 + nq * 16 + (lg >> 1) * 8 + lr;
                int kel  = kk + (lg & 1) * 8;
                ldmx4(b[nq], bhB + (unsigned)((nrow * APITCH + kel) * 2));
            }
#pragma unroll
            for (int mt = 0; mt < 2; mt++)
#pragma unroll
                for (int nt = 0; nt < 8; nt++) {
                    int nq = nt >> 1, h = (nt & 1) * 2;
                    mma_bf16(acc[mt][nt], ah[mt], b[nq][h], b[nq][h + 1]);
                }
#pragma unroll
            for (int mt = 0; mt < 2; mt++)
#pragma unroll
                for (int nt = 0; nt < 8; nt++) {
                    int nq = nt >> 1, h = (nt & 1) * 2;
                    mma_bf16(acc[mt][nt], al[mt], b[nq][h], b[nq][h + 1]);
                }
            // pass 3: b = Wlo ; acc += Ahi*Wlo
#pragma unroll
            for (int nq = 0; nq < 4; nq++) {
                int nrow = wn * 64 + nq * 16 + (lg >> 1) * 8 + lr;
                int kel  = kk + (lg & 1) * 8;
                ldmx4(b[nq], blB + (unsigned)((nrow * APITCH + kel) * 2));
            }
#pragma unroll
            for (int mt = 0; mt < 2; mt++)
#pragma unroll
                for (int nt = 0; nt < 8; nt++) {
                    int nq = nt >> 1, h = (nt & 1) * 2;
                    mma_bf16(acc[mt][nt], ah[mt], b[nq][h], b[nq][h + 1]);
                }
        }
        __syncthreads();
    }

    // epilogue
    const int group = lane >> 2;
    const int qt    = lane & 3;
#pragma unroll
    for (int mt = 0; mt < 2; mt++) {
#pragma unroll
        for (int nt = 0; nt < 8; nt++) {
            int row0 = rowBase + wm * 32 + mt * 16 + group;
            int col  = colBase + wn * 64 + nt * 8 + qt * 2;
            float b0v = 0.f, b1v = 0.f;
            if (bias) {
                if (col < M)     b0v = bias[col];
                if (col + 1 < M) b1v = bias[col + 1];
            }
            if (row0 < N) {
                if (col + 1 < M) {
                    float2 v = make_float2(acc[mt][nt][0] + b0v, acc[mt][nt][1] + b1v);
                    *reinterpret_cast<float2*>(C + (size_t)row0 * M + col) = v;
                } else if (col < M) {
                    C[(size_t)row0 * M + col] = acc[mt][nt][0] + b0v;
                }
            }
            int row1 = row0 + 8;
            if (row1 < N) {
                if (col + 1 < M) {
                    float2 v = make_float2(acc[mt][nt][2] + b0v, acc[mt][nt][3] + b1v);
                    *reinterpret_cast<float2*>(C + (size_t)row1 * M + col) = v;
                } else if (col < M) {
                    C[(size_t)row1 * M + col] = acc[mt][nt][2] + b0v;
                }
            }
        }
    }
}

// ---------------------------------------------------------------------------
// launch
// ---------------------------------------------------------------------------
extern "C" void kernel_launch(void* const* d_in, const int* in_sizes, int n_in,
                              void* d_out, int out_size) {
    const float* x  = (const float*)d_in[0];
    const int*   ei = (const int*)  d_in[1];
    const float* W1 = (const float*)d_in[2];
    const float* b1 = (const float*)d_in[3];
    const float* W2 = (const float*)d_in[4];
    const float* b2 = (const float*)d_in[5];
    const float* Wc = (const float*)d_in[6];
    const float* bc = (const float*)d_in[7];
    float* out = (float*)d_out;

    float *hP = nullptr, *aggP = nullptr;
    __nv_bfloat16 *w1hi, *w1lo, *w2hi, *w2lo, *wchi, *wclo;
    cudaGetSymbolAddress((void**)&hP,   g_h);
    cudaGetSymbolAddress((void**)&aggP, g_agg);
    cudaGetSymbolAddress((void**)&w1hi, g_w1hi);
    cudaGetSymbolAddress((void**)&w1lo, g_w1lo);
    cudaGetSymbolAddress((void**)&w2hi, g_w2hi);
    cudaGetSymbolAddress((void**)&w2lo, g_w2lo);
    cudaGetSymbolAddress((void**)&wchi, g_wchi);
    cudaGetSymbolAddress((void**)&wclo, g_wclo);

    // ---- CSR build + norms ----
    k_zero_cnt<<<(N_NODES + 255) / 256, 256>>>();
    k_count   <<<(N_EDGES + 255) / 256, 256>>>(ei);
    k_norm    <<<(N_NODES + 255) / 256, 256>>>();
    k_scan1   <<<SCAN_BLOCKS, 256>>>();
    k_scan2   <<<1, 256>>>();
    k_scan3   <<<SCAN_BLOCKS, 256>>>();
    k_fill    <<<(N_EDGES + 255) / 256, 256>>>(ei);

    // ---- weight splits ----
    const int WT2 = DIM * (DIM / 2);
    k_split_w<<<(WT2 + 255) / 256, 256>>>(W1, w1hi, w1lo, DIM);
    k_split_w<<<(WT2 + 255) / 256, 256>>>(W2, w2hi, w2lo, DIM);
    const int WC2 = NCLS * (DIM / 2);
    k_split_w<<<(WC2 + 255) / 256, 256>>>(Wc, wchi, wclo, NCLS);

    dim3 g1((DIM  + GBN - 1) / GBN, (N_NODES + GBM - 1) / GBM);   // (4, 391)
    dim3 g3((NCLS + GBN - 1) / GBN, (N_NODES + GBM - 1) / GBM);   // (1, 391)

    // ---- layer 1 ----
    k_gemm_fused<<<g1, 256>>>(x, w1hi, w1lo, hP, nullptr, N_NODES, DIM);
    k_gather    <<<N_NODES, 128>>>(hP, aggP, b1);

    // ---- layer 2 ----
    k_gemm_fused<<<g1, 256>>>(aggP, w2hi, w2lo, hP, nullptr, N_NODES, DIM);
    k_gather    <<<N_NODES, 128>>>(hP, aggP, b2);

    // ---- classifier ----
    k_gemm_fused<<<g3, 256>>>(aggP, wchi, wclo, out, bc, N_NODES, NCLS);
}

// round 6
// speedup vs baseline: 3.3799x; 1.3392x over previous
#include <cuda_runtime.h>
#include <cuda_bf16.h>
#include <cstdint>

#define N_NODES 50000
#define N_EDGES 500000
#define DIM     512
#define NCLS    100

// ---------------------------------------------------------------------------
// scratch (device globals)
// ---------------------------------------------------------------------------
__device__ float g_h  [(size_t)N_NODES * DIM];
__device__ float g_agg[(size_t)N_NODES * DIM];
__device__ float g_norm[N_NODES];
__device__ int   g_cnt [N_NODES];
__device__ int   g_fill[N_NODES];
__device__ int   g_off [N_NODES + 1];
__device__ int   g_csr_src [N_EDGES];
__device__ float g_csr_coef[N_EDGES];

__device__ __nv_bfloat16 g_w1hi[(size_t)DIM * DIM];
__device__ __nv_bfloat16 g_w1lo[(size_t)DIM * DIM];
__device__ __nv_bfloat16 g_w2hi[(size_t)DIM * DIM];
__device__ __nv_bfloat16 g_w2lo[(size_t)DIM * DIM];
__device__ __nv_bfloat16 g_wchi[(size_t)NCLS * DIM];
__device__ __nv_bfloat16 g_wclo[(size_t)NCLS * DIM];

#define SCAN_BLOCKS 196
__device__ int g_bsum[SCAN_BLOCKS];
__device__ int g_bpre[SCAN_BLOCKS];

// ---------------------------------------------------------------------------
// CSR build
// ---------------------------------------------------------------------------
__global__ void k_zero_cnt() {
    int i = blockIdx.x * blockDim.x + threadIdx.x;
    if (i < N_NODES) { g_cnt[i] = 0; g_fill[i] = 0; }
}

__global__ void k_count(const int* __restrict__ ei) {
    int e = blockIdx.x * blockDim.x + threadIdx.x;
    if (e < N_EDGES) atomicAdd(&g_cnt[ei[N_EDGES + e]], 1);
}

__global__ void k_norm() {
    int i = blockIdx.x * blockDim.x + threadIdx.x;
    if (i < N_NODES) g_norm[i] = rsqrtf(1.0f + (float)g_cnt[i]);
}

__device__ __forceinline__ int block_scan256(int v, int t, int* sh, int* tot) {
    int incl = v;
#pragma unroll
    for (int o = 1; o < 32; o <<= 1) {
        int u = __shfl_up_sync(0xffffffffu, incl, o);
        if ((t & 31) >= o) incl += u;
    }
    if ((t & 31) == 31) sh[t >> 5] = incl;
    __syncthreads();
    if (t < 8) {
        int w = sh[t];
        int iw = w;
#pragma unroll
        for (int o = 1; o < 8; o <<= 1) {
            int u = __shfl_up_sync(0xffu, iw, o);
            if (t >= o) iw += u;
        }
        sh[t] = iw - w;
        if (t == 7) *tot = iw;
    }
    __syncthreads();
    return incl + sh[t >> 5];
}

__global__ void __launch_bounds__(256) k_scan1() {
    __shared__ int sh[8]; __shared__ int tot;
    int i = blockIdx.x * 256 + threadIdx.x;
    int v = (i < N_NODES) ? g_cnt[i] : 0;
    block_scan256(v, threadIdx.x, sh, &tot);
    __syncthreads();
    if (threadIdx.x == 0) g_bsum[blockIdx.x] = tot;
}

__global__ void __launch_bounds__(256) k_scan2() {
    __shared__ int sh[8]; __shared__ int tot;
    int t = threadIdx.x;
    int v = (t < SCAN_BLOCKS) ? g_bsum[t] : 0;
    int incl = block_scan256(v, t, sh, &tot);
    if (t < SCAN_BLOCKS) g_bpre[t] = incl - v;
}

__global__ void __launch_bounds__(256) k_scan3() {
    __shared__ int sh[8]; __shared__ int tot;
    int i = blockIdx.x * 256 + threadIdx.x;
    int v = (i < N_NODES) ? g_cnt[i] : 0;
    int incl = block_scan256(v, threadIdx.x, sh, &tot);
    if (i < N_NODES) g_off[i + 1] = incl + g_bpre[blockIdx.x];
    if (i == 0) g_off[0] = 0;
}

__global__ void k_fill(const int* __restrict__ ei) {
    int e = blockIdx.x * blockDim.x + threadIdx.x;
    if (e >= N_EDGES) return;
    int src = ei[e];
    int dst = ei[N_EDGES + e];
    int pos = g_off[dst] + atomicAdd(&g_fill[dst], 1);
    g_csr_src [pos] = src;
    g_csr_coef[pos] = g_norm[src] * g_norm[dst];
}

// ---------------------------------------------------------------------------
// fp32 -> (hi, lo) bf16 split
// ---------------------------------------------------------------------------
__device__ __forceinline__ void split2(float2 a, unsigned& hi2, unsigned& lo2) {
    __nv_bfloat16 hx = __float2bfloat16(a.x);
    __nv_bfloat16 hy = __float2bfloat16(a.y);
    __nv_bfloat16 lx = __float2bfloat16(a.x - __bfloat162float(hx));
    __nv_bfloat16 ly = __float2bfloat16(a.y - __bfloat162float(hy));
    __nv_bfloat162 h = __halves2bfloat162(hx, hy);
    __nv_bfloat162 l = __halves2bfloat162(lx, ly);
    hi2 = *reinterpret_cast<unsigned*>(&h);
    lo2 = *reinterpret_cast<unsigned*>(&l);
}

__global__ void k_split_w(const float* __restrict__ src,
                          __nv_bfloat16* __restrict__ whi,
                          __nv_bfloat16* __restrict__ wlo, int n) {
    int i2 = blockIdx.x * blockDim.x + threadIdx.x;
    int total2 = n * (DIM / 2);
    if (i2 >= total2) return;
    float2 a = reinterpret_cast<const float2*>(src)[i2];
    unsigned hi2, lo2;
    split2(a, hi2, lo2);
    reinterpret_cast<unsigned*>(whi)[i2] = hi2;
    reinterpret_cast<unsigned*>(wlo)[i2] = lo2;
}

// ---------------------------------------------------------------------------
// gather aggregation (fused self-loop + bias + relu)
// ---------------------------------------------------------------------------
__global__ void __launch_bounds__(128) k_gather(const float* __restrict__ h,
                                                float* __restrict__ agg,
                                                const float* __restrict__ bias) {
    const int node = blockIdx.x;
    const int t    = threadIdx.x;
    const int beg  = g_off[node];
    const int end  = g_off[node + 1];

    float4 acc = make_float4(0.f, 0.f, 0.f, 0.f);
#pragma unroll 2
    for (int p = beg; p < end; p++) {
        int   src = g_csr_src[p];
        float c   = g_csr_coef[p];
        float4 v  = reinterpret_cast<const float4*>(h + (size_t)src * DIM)[t];
        acc.x = fmaf(c, v.x, acc.x);
        acc.y = fmaf(c, v.y, acc.y);
        acc.z = fmaf(c, v.z, acc.z);
        acc.w = fmaf(c, v.w, acc.w);
    }
    float cs = g_norm[node];
    cs = cs * cs;
    float4 hv = reinterpret_cast<const float4*>(h + (size_t)node * DIM)[t];
    float4 b  = reinterpret_cast<const float4*>(bias)[t];
    float4 r;
    r.x = fmaxf(fmaf(cs, hv.x, acc.x) + b.x, 0.f);
    r.y = fmaxf(fmaf(cs, hv.y, acc.y) + b.y, 0.f);
    r.z = fmaxf(fmaf(cs, hv.z, acc.z) + b.z, 0.f);
    r.w = fmaxf(fmaf(cs, hv.w, acc.w) + b.w, 0.f);
    reinterpret_cast<float4*>(agg + (size_t)node * DIM)[t] = r;
}

// ---------------------------------------------------------------------------
// pipelined fused split + bf16 mma.sync GEMM:
//   C[N,M] = A[N,512](fp32) * W[M,512]^T (+bias) via Ahi*Whi + Alo*Whi + Ahi*Wlo
// block 128x128, K-chunk 32, 256 threads (8 warps 4x2), warp tile 32x64.
// Double-buffered dynamic SMEM; W tiles via cp.async.cg, A via reg prefetch.
// ---------------------------------------------------------------------------
#define GBM 128
#define GBN 128
#define GBK 32
#define APITCH 40            // bf16 elems per SMEM row (80B pitch)
#define SEC    10240         // bytes per section (128 * 40 * 2)
#define STAGEB (4 * SEC)     // Ah, Al, Bh, Bl
#define SMEMB  (2 * STAGEB)  // 81920 bytes

__device__ __forceinline__ void mma_bf16(float* d, const unsigned* a,
                                         unsigned b0, unsigned b1) {
    asm volatile(
        "mma.sync.aligned.m16n8k16.row.col.f32.bf16.bf16.f32 "
        "{%0,%1,%2,%3}, {%4,%5,%6,%7}, {%8,%9}, {%0,%1,%2,%3};"
        : "+f"(d[0]), "+f"(d[1]), "+f"(d[2]), "+f"(d[3])
        : "r"(a[0]), "r"(a[1]), "r"(a[2]), "r"(a[3]), "r"(b0), "r"(b1));
}

__device__ __forceinline__ void ldmx4(unsigned* r, unsigned addr) {
    asm volatile(
        "ldmatrix.sync.aligned.m8n8.x4.shared.b16 {%0,%1,%2,%3}, [%4];"
        : "=r"(r[0]), "=r"(r[1]), "=r"(r[2]), "=r"(r[3])
        : "r"(addr));
}

__device__ __forceinline__ void cp_async16(uint32_t dst, const void* src) {
    asm volatile("cp.async.cg.shared.global [%0], [%1], 16;" :: "r"(dst), "l"(src) : "memory");
}
#define CP_COMMIT() asm volatile("cp.async.commit_group;" ::: "memory")
#define CP_WAIT0()  asm volatile("cp.async.wait_group 0;"  ::: "memory")

__global__ void __launch_bounds__(256) k_gemm_fused(const float* __restrict__ A,
                                                    const __nv_bfloat16* __restrict__ Whi,
                                                    const __nv_bfloat16* __restrict__ Wlo,
                                                    float* __restrict__ C,
                                                    const float* __restrict__ bias,
                                                    int N, int M) {
    extern __shared__ char smem[];
    uint32_t sb;
    asm("{ .reg .u64 t; cvta.to.shared.u64 t, %1; cvt.u32.u64 %0, t; }" : "=r"(sb) : "l"(smem));

    const int t    = threadIdx.x;
    const int lane = t & 31;
    const int warp = t >> 5;
    const int wm   = warp & 3;
    const int wn   = warp >> 2;
    const int rowBase = blockIdx.y * GBM;
    const int colBase = blockIdx.x * GBN;

    const int lg = lane >> 3;
    const int lr = lane & 7;

    // zero both stages (OOB lanes never overwrite -> stay zero)
#pragma unroll
    for (int i = 0; i < SMEMB / 16 / 256; i++)
        reinterpret_cast<uint4*>(smem)[i * 256 + t] = make_uint4(0, 0, 0, 0);
    __syncthreads();

    float acc[2][8][4];
#pragma unroll
    for (int i = 0; i < 2; i++)
#pragma unroll
        for (int j = 0; j < 8; j++)
#pragma unroll
            for (int q = 0; q < 4; q++) acc[i][j][q] = 0.f;

    // per-thread copy coordinates
    // A: chunk = t + L*256 ; r = chunk>>3 (8 float4 per 32-float row), c = chunk&7
    // B: chunk = t + L*256 ; r = chunk>>2 (4x16B per 32-bf16 row),    c = chunk&3

    // ---- prologue: stage 0 ----
    {
        const int k0 = 0;
        float4 aPre[4];
#pragma unroll
        for (int L = 0; L < 4; L++) {
            int chunk = t + L * 256;
            int r = chunk >> 3, c = chunk & 7;
            int gr = rowBase + r;
            if (gr < N) aPre[L] = *reinterpret_cast<const float4*>(A + (size_t)gr * DIM + k0 + c * 4);
        }
#pragma unroll
        for (int L = 0; L < 2; L++) {
            int chunk = t + L * 256;
            int r = chunk >> 2, c = chunk & 3;
            int gc = colBase + r;
            if (gc < M) {
                uint32_t off = (uint32_t)((r * APITCH + c * 8) * 2);
                cp_async16(sb + 2 * SEC + off, Whi + (size_t)gc * DIM + k0 + c * 8);
                cp_async16(sb + 3 * SEC + off, Wlo + (size_t)gc * DIM + k0 + c * 8);
            }
        }
        CP_COMMIT();
#pragma unroll
        for (int L = 0; L < 4; L++) {
            int chunk = t + L * 256;
            int r = chunk >> 3, c = chunk & 7;
            int gr = rowBase + r;
            if (gr < N) {
                unsigned h0, l0, h1, l1;
                split2(make_float2(aPre[L].x, aPre[L].y), h0, l0);
                split2(make_float2(aPre[L].z, aPre[L].w), h1, l1);
                uint32_t off = (uint32_t)((r * APITCH + c * 4) * 2);
                *reinterpret_cast<uint2*>(smem + off)       = make_uint2(h0, h1);
                *reinterpret_cast<uint2*>(smem + SEC + off) = make_uint2(l0, l1);
            }
        }
        CP_WAIT0();
        __syncthreads();
    }

    const int NITER = DIM / GBK;   // 16
    for (int it = 0; it < NITER; it++) {
        const int p    = it & 1;
        const bool pre = (it + 1 < NITER);
        const uint32_t cur = sb + (uint32_t)p * STAGEB;
        const uint32_t nxt = sb + (uint32_t)(p ^ 1) * STAGEB;

        float4 aPre[4];
        if (pre) {
            const int k1 = (it + 1) * GBK;
#pragma unroll
            for (int L = 0; L < 4; L++) {
                int chunk = t + L * 256;
                int r = chunk >> 3, c = chunk & 7;
                int gr = rowBase + r;
                if (gr < N) aPre[L] = *reinterpret_cast<const float4*>(A + (size_t)gr * DIM + k1 + c * 4);
            }
#pragma unroll
            for (int L = 0; L < 2; L++) {
                int chunk = t + L * 256;
                int r = chunk >> 2, c = chunk & 3;
                int gc = colBase + r;
                if (gc < M) {
                    uint32_t off = (uint32_t)((r * APITCH + c * 8) * 2);
                    cp_async16(nxt + 2 * SEC + off, Whi + (size_t)gc * DIM + k1 + c * 8);
                    cp_async16(nxt + 3 * SEC + off, Wlo + (size_t)gc * DIM + k1 + c * 8);
                }
            }
            CP_COMMIT();
        }

        // ---- compute current stage ----
#pragma unroll
        for (int kk = 0; kk < GBK; kk += 16) {
            unsigned ah[2][4], al[2][4];
#pragma unroll
            for (int mt = 0; mt < 2; mt++) {
                int row = wm * 32 + mt * 16 + (lg & 1) * 8 + lr;
                int kel = kk + (lg >> 1) * 8;
                unsigned off = (unsigned)((row * APITCH + kel) * 2);
                ldmx4(ah[mt], cur + off);
                ldmx4(al[mt], cur + SEC + off);
            }
            unsigned b[4][4];
#pragma unroll
            for (int nq = 0; nq < 4; nq++) {
                int nrow = wn * 64 + nq * 16 + (lg >> 1) * 8 + lr;
                int kel  = kk + (lg & 1) * 8;
                ldmx4(b[nq], cur + 2 * SEC + (unsigned)((nrow * APITCH + kel) * 2));
            }
#pragma unroll
            for (int mt = 0; mt < 2; mt++)
#pragma unroll
                for (int nt = 0; nt < 8; nt++) {
                    int nq = nt >> 1, h = (nt & 1) * 2;
                    mma_bf16(acc[mt][nt], ah[mt], b[nq][h], b[nq][h + 1]);
                }
#pragma unroll
            for (int mt = 0; mt < 2; mt++)
#pragma unroll
                for (int nt = 0; nt < 8; nt++) {
                    int nq = nt >> 1, h = (nt & 1) * 2;
                    mma_bf16(acc[mt][nt], al[mt], b[nq][h], b[nq][h + 1]);
                }
#pragma unroll
            for (int nq = 0; nq < 4; nq++) {
                int nrow = wn * 64 + nq * 16 + (lg >> 1) * 8 + lr;
                int kel  = kk + (lg & 1) * 8;
                ldmx4(b[nq], cur + 3 * SEC + (unsigned)((nrow * APITCH + kel) * 2));
            }
#pragma unroll
            for (int mt = 0; mt < 2; mt++)
#pragma unroll
                for (int nt = 0; nt < 8; nt++) {
                    int nq = nt >> 1, h = (nt & 1) * 2;
                    mma_bf16(acc[mt][nt], ah[mt], b[nq][h], b[nq][h + 1]);
                }
        }

        if (pre) {
            char* nxtg = smem + (size_t)(p ^ 1) * STAGEB;
#pragma unroll
            for (int L = 0; L < 4; L++) {
                int chunk = t + L * 256;
                int r = chunk >> 3, c = chunk & 7;
                int gr = rowBase + r;
                if (gr < N) {
                    unsigned h0, l0, h1, l1;
                    split2(make_float2(aPre[L].x, aPre[L].y), h0, l0);
                    split2(make_float2(aPre[L].z, aPre[L].w), h1, l1);
                    uint32_t off = (uint32_t)((r * APITCH + c * 4) * 2);
                    *reinterpret_cast<uint2*>(nxtg + off)       = make_uint2(h0, h1);
                    *reinterpret_cast<uint2*>(nxtg + SEC + off) = make_uint2(l0, l1);
                }
            }
            CP_WAIT0();
        }
        __syncthreads();
    }

    // epilogue
    const int group = lane >> 2;
    const int qt    = lane & 3;
#pragma unroll
    for (int mt = 0; mt < 2; mt++) {
#pragma unroll
        for (int nt = 0; nt < 8; nt++) {
            int row0 = rowBase + wm * 32 + mt * 16 + group;
            int col  = colBase + wn * 64 + nt * 8 + qt * 2;
            float b0v = 0.f, b1v = 0.f;
            if (bias) {
                if (col < M)     b0v = bias[col];
                if (col + 1 < M) b1v = bias[col + 1];
            }
            if (row0 < N) {
                if (col + 1 < M) {
                    float2 v = make_float2(acc[mt][nt][0] + b0v, acc[mt][nt][1] + b1v);
                    *reinterpret_cast<float2*>(C + (size_t)row0 * M + col) = v;
                } else if (col < M) {
                    C[(size_t)row0 * M + col] = acc[mt][nt][0] + b0v;
                }
            }
            int row1 = row0 + 8;
            if (row1 < N) {
                if (col + 1 < M) {
                    float2 v = make_float2(acc[mt][nt][2] + b0v, acc[mt][nt][3] + b1v);
                    *reinterpret_cast<float2*>(C + (size_t)row1 * M + col) = v;
                } else if (col < M) {
                    C[(size_t)row1 * M + col] = acc[mt][nt][2] + b0v;
                }
            }
        }
    }
}

// ---------------------------------------------------------------------------
// launch
// ---------------------------------------------------------------------------
extern "C" void kernel_launch(void* const* d_in, const int* in_sizes, int n_in,
                              void* d_out, int out_size) {
    const float* x  = (const float*)d_in[0];
    const int*   ei = (const int*)  d_in[1];
    const float* W1 = (const float*)d_in[2];
    const float* b1 = (const float*)d_in[3];
    const float* W2 = (const float*)d_in[4];
    const float* b2 = (const float*)d_in[5];
    const float* Wc = (const float*)d_in[6];
    const float* bc = (const float*)d_in[7];
    float* out = (float*)d_out;

    float *hP = nullptr, *aggP = nullptr;
    __nv_bfloat16 *w1hi, *w1lo, *w2hi, *w2lo, *wchi, *wclo;
    cudaGetSymbolAddress((void**)&hP,   g_h);
    cudaGetSymbolAddress((void**)&aggP, g_agg);
    cudaGetSymbolAddress((void**)&w1hi, g_w1hi);
    cudaGetSymbolAddress((void**)&w1lo, g_w1lo);
    cudaGetSymbolAddress((void**)&w2hi, g_w2hi);
    cudaGetSymbolAddress((void**)&w2lo, g_w2lo);
    cudaGetSymbolAddress((void**)&wchi, g_wchi);
    cudaGetSymbolAddress((void**)&wclo, g_wclo);

    cudaFuncSetAttribute(k_gemm_fused, cudaFuncAttributeMaxDynamicSharedMemorySize, SMEMB);

    // ---- CSR build + norms ----
    k_zero_cnt<<<(N_NODES + 255) / 256, 256>>>();
    k_count   <<<(N_EDGES + 255) / 256, 256>>>(ei);
    k_norm    <<<(N_NODES + 255) / 256, 256>>>();
    k_scan1   <<<SCAN_BLOCKS, 256>>>();
    k_scan2   <<<1, 256>>>();
    k_scan3   <<<SCAN_BLOCKS, 256>>>();
    k_fill    <<<(N_EDGES + 255) / 256, 256>>>(ei);

    // ---- weight splits ----
    const int WT2 = DIM * (DIM / 2);
    k_split_w<<<(WT2 + 255) / 256, 256>>>(W1, w1hi, w1lo, DIM);
    k_split_w<<<(WT2 + 255) / 256, 256>>>(W2, w2hi, w2lo, DIM);
    const int WC2 = NCLS * (DIM / 2);
    k_split_w<<<(WC2 + 255) / 256, 256>>>(Wc, wchi, wclo, NCLS);

    dim3 g1((DIM  + GBN - 1) / GBN, (N_NODES + GBM - 1) / GBM);   // (4, 391)
    dim3 g3((NCLS + GBN - 1) / GBN, (N_NODES + GBM - 1) / GBM);   // (1, 391)

    // ---- layer 1 ----
    k_gemm_fused<<<g1, 256, SMEMB>>>(x, w1hi, w1lo, hP, nullptr, N_NODES, DIM);
    k_gather    <<<N_NODES, 128>>>(hP, aggP, b1);

    // ---- layer 2 ----
    k_gemm_fused<<<g1, 256, SMEMB>>>(aggP, w2hi, w2lo, hP, nullptr, N_NODES, DIM);
    k_gather    <<<N_NODES, 128>>>(hP, aggP, b2);

    // ---- classifier ----
    k_gemm_fused<<<g3, 256, SMEMB>>>(aggP, wchi, wclo, out, bc, N_NODES, NCLS);
}

// round 7
// speedup vs baseline: 3.4223x; 1.0126x over previous
#include <cuda_runtime.h>
#include <cuda_bf16.h>
#include <cstdint>

#define N_NODES 50000
#define N_EDGES 500000
#define DIM     512
#define NCLS    100

// ---------------------------------------------------------------------------
// scratch (device globals)
// ---------------------------------------------------------------------------
__device__ float g_h  [(size_t)N_NODES * DIM];
__device__ float g_agg[(size_t)N_NODES * DIM];
__device__ float g_norm[N_NODES];
__device__ int   g_cnt [N_NODES];
__device__ int   g_fill[N_NODES];
__device__ int   g_off [N_NODES + 1];
__device__ int   g_csr_src [N_EDGES];
__device__ float g_csr_coef[N_EDGES];

__device__ __nv_bfloat16 g_w1hi[(size_t)DIM * DIM];
__device__ __nv_bfloat16 g_w1lo[(size_t)DIM * DIM];
__device__ __nv_bfloat16 g_w2hi[(size_t)DIM * DIM];
__device__ __nv_bfloat16 g_w2lo[(size_t)DIM * DIM];
__device__ __nv_bfloat16 g_wchi[(size_t)NCLS * DIM];
__device__ __nv_bfloat16 g_wclo[(size_t)NCLS * DIM];

#define SCAN_BLOCKS 196
__device__ int g_bsum[SCAN_BLOCKS];
__device__ int g_bpre[SCAN_BLOCKS];

// ---------------------------------------------------------------------------
// CSR build
// ---------------------------------------------------------------------------
__global__ void k_zero_cnt() {
    int i = blockIdx.x * blockDim.x + threadIdx.x;
    if (i < N_NODES) { g_cnt[i] = 0; g_fill[i] = 0; }
}

__global__ void k_count(const int* __restrict__ ei) {
    int e = blockIdx.x * blockDim.x + threadIdx.x;
    if (e < N_EDGES) atomicAdd(&g_cnt[ei[N_EDGES + e]], 1);
}

__global__ void k_norm() {
    int i = blockIdx.x * blockDim.x + threadIdx.x;
    if (i < N_NODES) g_norm[i] = rsqrtf(1.0f + (float)g_cnt[i]);
}

__device__ __forceinline__ int block_scan256(int v, int t, int* sh, int* tot) {
    int incl = v;
#pragma unroll
    for (int o = 1; o < 32; o <<= 1) {
        int u = __shfl_up_sync(0xffffffffu, incl, o);
        if ((t & 31) >= o) incl += u;
    }
    if ((t & 31) == 31) sh[t >> 5] = incl;
    __syncthreads();
    if (t < 8) {
        int w = sh[t];
        int iw = w;
#pragma unroll
        for (int o = 1; o < 8; o <<= 1) {
            int u = __shfl_up_sync(0xffu, iw, o);
            if (t >= o) iw += u;
        }
        sh[t] = iw - w;
        if (t == 7) *tot = iw;
    }
    __syncthreads();
    return incl + sh[t >> 5];
}

__global__ void __launch_bounds__(256) k_scan1() {
    __shared__ int sh[8]; __shared__ int tot;
    int i = blockIdx.x * 256 + threadIdx.x;
    int v = (i < N_NODES) ? g_cnt[i] : 0;
    block_scan256(v, threadIdx.x, sh, &tot);
    __syncthreads();
    if (threadIdx.x == 0) g_bsum[blockIdx.x] = tot;
}

__global__ void __launch_bounds__(256) k_scan2() {
    __shared__ int sh[8]; __shared__ int tot;
    int t = threadIdx.x;
    int v = (t < SCAN_BLOCKS) ? g_bsum[t] : 0;
    int incl = block_scan256(v, t, sh, &tot);
    if (t < SCAN_BLOCKS) g_bpre[t] = incl - v;
}

__global__ void __launch_bounds__(256) k_scan3() {
    __shared__ int sh[8]; __shared__ int tot;
    int i = blockIdx.x * 256 + threadIdx.x;
    int v = (i < N_NODES) ? g_cnt[i] : 0;
    int incl = block_scan256(v, threadIdx.x, sh, &tot);
    if (i < N_NODES) g_off[i + 1] = incl + g_bpre[blockIdx.x];
    if (i == 0) g_off[0] = 0;
}

__global__ void k_fill(const int* __restrict__ ei) {
    int e = blockIdx.x * blockDim.x + threadIdx.x;
    if (e >= N_EDGES) return;
    int src = ei[e];
    int dst = ei[N_EDGES + e];
    int pos = g_off[dst] + atomicAdd(&g_fill[dst], 1);
    g_csr_src [pos] = src;
    g_csr_coef[pos] = g_norm[src] * g_norm[dst];
}

// ---------------------------------------------------------------------------
// fp32 -> (hi, lo) bf16 split
// ---------------------------------------------------------------------------
__device__ __forceinline__ void split2(float2 a, unsigned& hi2, unsigned& lo2) {
    __nv_bfloat16 hx = __float2bfloat16(a.x);
    __nv_bfloat16 hy = __float2bfloat16(a.y);
    __nv_bfloat16 lx = __float2bfloat16(a.x - __bfloat162float(hx));
    __nv_bfloat16 ly = __float2bfloat16(a.y - __bfloat162float(hy));
    __nv_bfloat162 h = __halves2bfloat162(hx, hy);
    __nv_bfloat162 l = __halves2bfloat162(lx, ly);
    hi2 = *reinterpret_cast<unsigned*>(&h);
    lo2 = *reinterpret_cast<unsigned*>(&l);
}

__global__ void k_split_w(const float* __restrict__ src,
                          __nv_bfloat16* __restrict__ whi,
                          __nv_bfloat16* __restrict__ wlo, int n) {
    int i2 = blockIdx.x * blockDim.x + threadIdx.x;
    int total2 = n * (DIM / 2);
    if (i2 >= total2) return;
    float2 a = reinterpret_cast<const float2*>(src)[i2];
    unsigned hi2, lo2;
    split2(a, hi2, lo2);
    reinterpret_cast<unsigned*>(whi)[i2] = hi2;
    reinterpret_cast<unsigned*>(wlo)[i2] = lo2;
}

// ---------------------------------------------------------------------------
// gather aggregation (fused self-loop + bias + relu), unroll-4 prefetch
// ---------------------------------------------------------------------------
__global__ void __launch_bounds__(128) k_gather(const float* __restrict__ h,
                                                float* __restrict__ agg,
                                                const float* __restrict__ bias) {
    const int node = blockIdx.x;
    const int t    = threadIdx.x;
    const int beg  = g_off[node];
    const int end  = g_off[node + 1];

    float4 acc = make_float4(0.f, 0.f, 0.f, 0.f);

    int p = beg;
    for (; p + 4 <= end; p += 4) {
        // index/coef loads are warp-uniform broadcasts; row loads independent (MLP=4)
        int   s0 = __ldg(&g_csr_src[p]),     s1 = __ldg(&g_csr_src[p + 1]);
        int   s2 = __ldg(&g_csr_src[p + 2]), s3 = __ldg(&g_csr_src[p + 3]);
        float c0 = __ldg(&g_csr_coef[p]),     c1 = __ldg(&g_csr_coef[p + 1]);
        float c2 = __ldg(&g_csr_coef[p + 2]), c3 = __ldg(&g_csr_coef[p + 3]);
        float4 v0 = reinterpret_cast<const float4*>(h + (size_t)s0 * DIM)[t];
        float4 v1 = reinterpret_cast<const float4*>(h + (size_t)s1 * DIM)[t];
        float4 v2 = reinterpret_cast<const float4*>(h + (size_t)s2 * DIM)[t];
        float4 v3 = reinterpret_cast<const float4*>(h + (size_t)s3 * DIM)[t];
        acc.x = fmaf(c0, v0.x, acc.x); acc.y = fmaf(c0, v0.y, acc.y);
        acc.z = fmaf(c0, v0.z, acc.z); acc.w = fmaf(c0, v0.w, acc.w);
        acc.x = fmaf(c1, v1.x, acc.x); acc.y = fmaf(c1, v1.y, acc.y);
        acc.z = fmaf(c1, v1.z, acc.z); acc.w = fmaf(c1, v1.w, acc.w);
        acc.x = fmaf(c2, v2.x, acc.x); acc.y = fmaf(c2, v2.y, acc.y);
        acc.z = fmaf(c2, v2.z, acc.z); acc.w = fmaf(c2, v2.w, acc.w);
        acc.x = fmaf(c3, v3.x, acc.x); acc.y = fmaf(c3, v3.y, acc.y);
        acc.z = fmaf(c3, v3.z, acc.z); acc.w = fmaf(c3, v3.w, acc.w);
    }
    for (; p < end; p++) {
        int   src = g_csr_src[p];
        float c   = g_csr_coef[p];
        float4 v  = reinterpret_cast<const float4*>(h + (size_t)src * DIM)[t];
        acc.x = fmaf(c, v.x, acc.x);
        acc.y = fmaf(c, v.y, acc.y);
        acc.z = fmaf(c, v.z, acc.z);
        acc.w = fmaf(c, v.w, acc.w);
    }

    float cs = g_norm[node];
    cs = cs * cs;
    float4 hv = reinterpret_cast<const float4*>(h + (size_t)node * DIM)[t];
    float4 b  = reinterpret_cast<const float4*>(bias)[t];
    float4 r;
    r.x = fmaxf(fmaf(cs, hv.x, acc.x) + b.x, 0.f);
    r.y = fmaxf(fmaf(cs, hv.y, acc.y) + b.y, 0.f);
    r.z = fmaxf(fmaf(cs, hv.z, acc.z) + b.z, 0.f);
    r.w = fmaxf(fmaf(cs, hv.w, acc.w) + b.w, 0.f);
    reinterpret_cast<float4*>(agg + (size_t)node * DIM)[t] = r;
}

// ---------------------------------------------------------------------------
// pipelined fused split + bf16 mma.sync GEMM  (unchanged from R6 — 885 µs)
// ---------------------------------------------------------------------------
#define GBM 128
#define GBN 128
#define GBK 32
#define APITCH 40
#define SEC    10240
#define STAGEB (4 * SEC)
#define SMEMB  (2 * STAGEB)

__device__ __forceinline__ void mma_bf16(float* d, const unsigned* a,
                                         unsigned b0, unsigned b1) {
    asm volatile(
        "mma.sync.aligned.m16n8k16.row.col.f32.bf16.bf16.f32 "
        "{%0,%1,%2,%3}, {%4,%5,%6,%7}, {%8,%9}, {%0,%1,%2,%3};"
        : "+f"(d[0]), "+f"(d[1]), "+f"(d[2]), "+f"(d[3])
        : "r"(a[0]), "r"(a[1]), "r"(a[2]), "r"(a[3]), "r"(b0), "r"(b1));
}

__device__ __forceinline__ void ldmx4(unsigned* r, unsigned addr) {
    asm volatile(
        "ldmatrix.sync.aligned.m8n8.x4.shared.b16 {%0,%1,%2,%3}, [%4];"
        : "=r"(r[0]), "=r"(r[1]), "=r"(r[2]), "=r"(r[3])
        : "r"(addr));
}

__device__ __forceinline__ void cp_async16(uint32_t dst, const void* src) {
    asm volatile("cp.async.cg.shared.global [%0], [%1], 16;" :: "r"(dst), "l"(src) : "memory");
}
#define CP_COMMIT() asm volatile("cp.async.commit_group;" ::: "memory")
#define CP_WAIT0()  asm volatile("cp.async.wait_group 0;"  ::: "memory")

__global__ void __launch_bounds__(256) k_gemm_fused(const float* __restrict__ A,
                                                    const __nv_bfloat16* __restrict__ Whi,
                                                    const __nv_bfloat16* __restrict__ Wlo,
                                                    float* __restrict__ C,
                                                    const float* __restrict__ bias,
                                                    int N, int M) {
    extern __shared__ char smem[];
    uint32_t sb;
    asm("{ .reg .u64 t; cvta.to.shared.u64 t, %1; cvt.u32.u64 %0, t; }" : "=r"(sb) : "l"(smem));

    const int t    = threadIdx.x;
    const int lane = t & 31;
    const int warp = t >> 5;
    const int wm   = warp & 3;
    const int wn   = warp >> 2;
    const int rowBase = blockIdx.y * GBM;
    const int colBase = blockIdx.x * GBN;

    const int lg = lane >> 3;
    const int lr = lane & 7;

#pragma unroll
    for (int i = 0; i < SMEMB / 16 / 256; i++)
        reinterpret_cast<uint4*>(smem)[i * 256 + t] = make_uint4(0, 0, 0, 0);
    __syncthreads();

    float acc[2][8][4];
#pragma unroll
    for (int i = 0; i < 2; i++)
#pragma unroll
        for (int j = 0; j < 8; j++)
#pragma unroll
            for (int q = 0; q < 4; q++) acc[i][j][q] = 0.f;

    // ---- prologue: stage 0 ----
    {
        const int k0 = 0;
        float4 aPre[4];
#pragma unroll
        for (int L = 0; L < 4; L++) {
            int chunk = t + L * 256;
            int r = chunk >> 3, c = chunk & 7;
            int gr = rowBase + r;
            if (gr < N) aPre[L] = *reinterpret_cast<const float4*>(A + (size_t)gr * DIM + k0 + c * 4);
        }
#pragma unroll
        for (int L = 0; L < 2; L++) {
            int chunk = t + L * 256;
            int r = chunk >> 2, c = chunk & 3;
            int gc = colBase + r;
            if (gc < M) {
                uint32_t off = (uint32_t)((r * APITCH + c * 8) * 2);
                cp_async16(sb + 2 * SEC + off, Whi + (size_t)gc * DIM + k0 + c * 8);
                cp_async16(sb + 3 * SEC + off, Wlo + (size_t)gc * DIM + k0 + c * 8);
            }
        }
        CP_COMMIT();
#pragma unroll
        for (int L = 0; L < 4; L++) {
            int chunk = t + L * 256;
            int r = chunk >> 3, c = chunk & 7;
            int gr = rowBase + r;
            if (gr < N) {
                unsigned h0, l0, h1, l1;
                split2(make_float2(aPre[L].x, aPre[L].y), h0, l0);
                split2(make_float2(aPre[L].z, aPre[L].w), h1, l1);
                uint32_t off = (uint32_t)((r * APITCH + c * 4) * 2);
                *reinterpret_cast<uint2*>(smem + off)       = make_uint2(h0, h1);
                *reinterpret_cast<uint2*>(smem + SEC + off) = make_uint2(l0, l1);
            }
        }
        CP_WAIT0();
        __syncthreads();
    }

    const int NITER = DIM / GBK;   // 16
    for (int it = 0; it < NITER; it++) {
        const int p    = it & 1;
        const bool pre = (it + 1 < NITER);
        const uint32_t cur = sb + (uint32_t)p * STAGEB;
        const uint32_t nxt = sb + (uint32_t)(p ^ 1) * STAGEB;

        float4 aPre[4];
        if (pre) {
            const int k1 = (it + 1) * GBK;
#pragma unroll
            for (int L = 0; L < 4; L++) {
                int chunk = t + L * 256;
                int r = chunk >> 3, c = chunk & 7;
                int gr = rowBase + r;
                if (gr < N) aPre[L] = *reinterpret_cast<const float4*>(A + (size_t)gr * DIM + k1 + c * 4);
            }
#pragma unroll
            for (int L = 0; L < 2; L++) {
                int chunk = t + L * 256;
                int r = chunk >> 2, c = chunk & 3;
                int gc = colBase + r;
                if (gc < M) {
                    uint32_t off = (uint32_t)((r * APITCH + c * 8) * 2);
                    cp_async16(nxt + 2 * SEC + off, Whi + (size_t)gc * DIM + k1 + c * 8);
                    cp_async16(nxt + 3 * SEC + off, Wlo + (size_t)gc * DIM + k1 + c * 8);
                }
            }
            CP_COMMIT();
        }

#pragma unroll
        for (int kk = 0; kk < GBK; kk += 16) {
            unsigned ah[2][4], al[2][4];
#pragma unroll
            for (int mt = 0; mt < 2; mt++) {
                int row = wm * 32 + mt * 16 + (lg & 1) * 8 + lr;
                int kel = kk + (lg >> 1) * 8;
                unsigned off = (unsigned)((row * APITCH + kel) * 2);
                ldmx4(ah[mt], cur + off);
                ldmx4(al[mt], cur + SEC + off);
            }
            unsigned b[4][4];
#pragma unroll
            for (int nq = 0; nq < 4; nq++) {
                int nrow = wn * 64 + nq * 16 + (lg >> 1) * 8 + lr;
                int kel  = kk + (lg & 1) * 8;
                ldmx4(b[nq], cur + 2 * SEC + (unsigned)((nrow * APITCH + kel) * 2));
            }
#pragma unroll
            for (int mt = 0; mt < 2; mt++)
#pragma unroll
                for (int nt = 0; nt < 8; nt++) {
                    int nq = nt >> 1, h = (nt & 1) * 2;
                    mma_bf16(acc[mt][nt], ah[mt], b[nq][h], b[nq][h + 1]);
                }
#pragma unroll
            for (int mt = 0; mt < 2; mt++)
#pragma unroll
                for (int nt = 0; nt < 8; nt++) {
                    int nq = nt >> 1, h = (nt & 1) * 2;
                    mma_bf16(acc[mt][nt], al[mt], b[nq][h], b[nq][h + 1]);
                }
#pragma unroll
            for (int nq = 0; nq < 4; nq++) {
                int nrow = wn * 64 + nq * 16 + (lg >> 1) * 8 + lr;
                int kel  = kk + (lg & 1) * 8;
                ldmx4(b[nq], cur + 3 * SEC + (unsigned)((nrow * APITCH + kel) * 2));
            }
#pragma unroll
            for (int mt = 0; mt < 2; mt++)
#pragma unroll
                for (int nt = 0; nt < 8; nt++) {
                    int nq = nt >> 1, h = (nt & 1) * 2;
                    mma_bf16(acc[mt][nt], ah[mt], b[nq][h], b[nq][h + 1]);
                }
        }

        if (pre) {
            char* nxtg = smem + (size_t)(p ^ 1) * STAGEB;
#pragma unroll
            for (int L = 0; L < 4; L++) {
                int chunk = t + L * 256;
                int r = chunk >> 3, c = chunk & 7;
                int gr = rowBase + r;
                if (gr < N) {
                    unsigned h0, l0, h1, l1;
                    split2(make_float2(aPre[L].x, aPre[L].y), h0, l0);
                    split2(make_float2(aPre[L].z, aPre[L].w), h1, l1);
                    uint32_t off = (uint32_t)((r * APITCH + c * 4) * 2);
                    *reinterpret_cast<uint2*>(nxtg + off)       = make_uint2(h0, h1);
                    *reinterpret_cast<uint2*>(nxtg + SEC + off) = make_uint2(l0, l1);
                }
            }
            CP_WAIT0();
        }
        __syncthreads();
    }

    // epilogue
    const int group = lane >> 2;
    const int qt    = lane & 3;
#pragma unroll
    for (int mt = 0; mt < 2; mt++) {
#pragma unroll
        for (int nt = 0; nt < 8; nt++) {
            int row0 = rowBase + wm * 32 + mt * 16 + group;
            int col  = colBase + wn * 64 + nt * 8 + qt * 2;
            float b0v = 0.f, b1v = 0.f;
            if (bias) {
                if (col < M)     b0v = bias[col];
                if (col + 1 < M) b1v = bias[col + 1];
            }
            if (row0 < N) {
                if (col + 1 < M) {
                    float2 v = make_float2(acc[mt][nt][0] + b0v, acc[mt][nt][1] + b1v);
                    *reinterpret_cast<float2*>(C + (size_t)row0 * M + col) = v;
                } else if (col < M) {
                    C[(size_t)row0 * M + col] = acc[mt][nt][0] + b0v;
                }
            }
            int row1 = row0 + 8;
            if (row1 < N) {
                if (col + 1 < M) {
                    float2 v = make_float2(acc[mt][nt][2] + b0v, acc[mt][nt][3] + b1v);
                    *reinterpret_cast<float2*>(C + (size_t)row1 * M + col) = v;
                } else if (col < M) {
                    C[(size_t)row1 * M + col] = acc[mt][nt][2] + b0v;
                }
            }
        }
    }
}

// ---------------------------------------------------------------------------
// launch
// ---------------------------------------------------------------------------
extern "C" void kernel_launch(void* const* d_in, const int* in_sizes, int n_in,
                              void* d_out, int out_size) {
    const float* x  = (const float*)d_in[0];
    const int*   ei = (const int*)  d_in[1];
    const float* W1 = (const float*)d_in[2];
    const float* b1 = (const float*)d_in[3];
    const float* W2 = (const float*)d_in[4];
    const float* b2 = (const float*)d_in[5];
    const float* Wc = (const float*)d_in[6];
    const float* bc = (const float*)d_in[7];
    float* out = (float*)d_out;

    float *hP = nullptr, *aggP = nullptr;
    __nv_bfloat16 *w1hi, *w1lo, *w2hi, *w2lo, *wchi, *wclo;
    cudaGetSymbolAddress((void**)&hP,   g_h);
    cudaGetSymbolAddress((void**)&aggP, g_agg);
    cudaGetSymbolAddress((void**)&w1hi, g_w1hi);
    cudaGetSymbolAddress((void**)&w1lo, g_w1lo);
    cudaGetSymbolAddress((void**)&w2hi, g_w2hi);
    cudaGetSymbolAddress((void**)&w2lo, g_w2lo);
    cudaGetSymbolAddress((void**)&wchi, g_wchi);
    cudaGetSymbolAddress((void**)&wclo, g_wclo);

    cudaFuncSetAttribute(k_gemm_fused, cudaFuncAttributeMaxDynamicSharedMemorySize, SMEMB);

    // ---- CSR build + norms ----
    k_zero_cnt<<<(N_NODES + 255) / 256, 256>>>();
    k_count   <<<(N_EDGES + 255) / 256, 256>>>(ei);
    k_norm    <<<(N_NODES + 255) / 256, 256>>>();
    k_scan1   <<<SCAN_BLOCKS, 256>>>();
    k_scan2   <<<1, 256>>>();
    k_scan3   <<<SCAN_BLOCKS, 256>>>();
    k_fill    <<<(N_EDGES + 255) / 256, 256>>>(ei);

    // ---- weight splits ----
    const int WT2 = DIM * (DIM / 2);
    k_split_w<<<(WT2 + 255) / 256, 256>>>(W1, w1hi, w1lo, DIM);
    k_split_w<<<(WT2 + 255) / 256, 256>>>(W2, w2hi, w2lo, DIM);
    const int WC2 = NCLS * (DIM / 2);
    k_split_w<<<(WC2 + 255) / 256, 256>>>(Wc, wchi, wclo, NCLS);

    dim3 g1((DIM  + GBN - 1) / GBN, (N_NODES + GBM - 1) / GBM);   // (4, 391)
    dim3 g3((NCLS + GBN - 1) / GBN, (N_NODES + GBM - 1) / GBM);   // (1, 391)

    // ---- layer 1 ----
    k_gemm_fused<<<g1, 256, SMEMB>>>(x, w1hi, w1lo, hP, nullptr, N_NODES, DIM);
    k_gather    <<<N_NODES, 128>>>(hP, aggP, b1);

    // ---- layer 2 ----
    k_gemm_fused<<<g1, 256, SMEMB>>>(aggP, w2hi, w2lo, hP, nullptr, N_NODES, DIM);
    k_gather    <<<N_NODES, 128>>>(hP, aggP, b2);

    // ---- classifier ----
    k_gemm_fused<<<g3, 256, SMEMB>>>(aggP, wchi, wclo, out, bc, N_NODES, NCLS);
}

// round 8
// speedup vs baseline: 3.5379x; 1.0338x over previous
#include <cuda_runtime.h>
#include <cuda_bf16.h>
#include <cstdint>

#define N_NODES 50000
#define N_EDGES 500000
#define DIM     512
#define NCLS    100

// ---------------------------------------------------------------------------
// scratch (device globals)
// ---------------------------------------------------------------------------
__device__ float g_h  [(size_t)N_NODES * DIM];
__device__ float g_agg[(size_t)N_NODES * DIM];
__device__ float g_norm[N_NODES];
__device__ int   g_cnt [N_NODES];
__device__ int   g_fill[N_NODES];
__device__ int   g_off [N_NODES + 1];
__device__ int   g_csr_src [N_EDGES];
__device__ float g_csr_coef[N_EDGES];

__device__ __nv_bfloat16 g_w1hi[(size_t)DIM * DIM];
__device__ __nv_bfloat16 g_w1lo[(size_t)DIM * DIM];
__device__ __nv_bfloat16 g_w2hi[(size_t)DIM * DIM];
__device__ __nv_bfloat16 g_w2lo[(size_t)DIM * DIM];
__device__ __nv_bfloat16 g_wchi[(size_t)NCLS * DIM];
__device__ __nv_bfloat16 g_wclo[(size_t)NCLS * DIM];

#define SCAN_BLOCKS 196
__device__ int g_bsum[SCAN_BLOCKS];
__device__ int g_bpre[SCAN_BLOCKS];

// ---------------------------------------------------------------------------
// CSR build
// ---------------------------------------------------------------------------
__global__ void k_zero_cnt() {
    int i = blockIdx.x * blockDim.x + threadIdx.x;
    if (i < N_NODES) { g_cnt[i] = 0; g_fill[i] = 0; }
}

__global__ void k_count(const int* __restrict__ ei) {
    int e = blockIdx.x * blockDim.x + threadIdx.x;
    if (e < N_EDGES) atomicAdd(&g_cnt[ei[N_EDGES + e]], 1);
}

__global__ void k_norm() {
    int i = blockIdx.x * blockDim.x + threadIdx.x;
    if (i < N_NODES) g_norm[i] = rsqrtf(1.0f + (float)g_cnt[i]);
}

__device__ __forceinline__ int block_scan256(int v, int t, int* sh, int* tot) {
    int incl = v;
#pragma unroll
    for (int o = 1; o < 32; o <<= 1) {
        int u = __shfl_up_sync(0xffffffffu, incl, o);
        if ((t & 31) >= o) incl += u;
    }
    if ((t & 31) == 31) sh[t >> 5] = incl;
    __syncthreads();
    if (t < 8) {
        int w = sh[t];
        int iw = w;
#pragma unroll
        for (int o = 1; o < 8; o <<= 1) {
            int u = __shfl_up_sync(0xffu, iw, o);
            if (t >= o) iw += u;
        }
        sh[t] = iw - w;
        if (t == 7) *tot = iw;
    }
    __syncthreads();
    return incl + sh[t >> 5];
}

__global__ void __launch_bounds__(256) k_scan1() {
    __shared__ int sh[8]; __shared__ int tot;
    int i = blockIdx.x * 256 + threadIdx.x;
    int v = (i < N_NODES) ? g_cnt[i] : 0;
    block_scan256(v, threadIdx.x, sh, &tot);
    __syncthreads();
    if (threadIdx.x == 0) g_bsum[blockIdx.x] = tot;
}

__global__ void __launch_bounds__(256) k_scan2() {
    __shared__ int sh[8]; __shared__ int tot;
    int t = threadIdx.x;
    int v = (t < SCAN_BLOCKS) ? g_bsum[t] : 0;
    int incl = block_scan256(v, t, sh, &tot);
    if (t < SCAN_BLOCKS) g_bpre[t] = incl - v;
}

__global__ void __launch_bounds__(256) k_scan3() {
    __shared__ int sh[8]; __shared__ int tot;
    int i = blockIdx.x * 256 + threadIdx.x;
    int v = (i < N_NODES) ? g_cnt[i] : 0;
    int incl = block_scan256(v, threadIdx.x, sh, &tot);
    if (i < N_NODES) g_off[i + 1] = incl + g_bpre[blockIdx.x];
    if (i == 0) g_off[0] = 0;
}

__global__ void k_fill(const int* __restrict__ ei) {
    int e = blockIdx.x * blockDim.x + threadIdx.x;
    if (e >= N_EDGES) return;
    int src = ei[e];
    int dst = ei[N_EDGES + e];
    int pos = g_off[dst] + atomicAdd(&g_fill[dst], 1);
    g_csr_src [pos] = src;
    g_csr_coef[pos] = g_norm[src] * g_norm[dst];
}

// ---------------------------------------------------------------------------
// fp32 -> (hi, lo) bf16 split
// ---------------------------------------------------------------------------
__device__ __forceinline__ void split2(float2 a, unsigned& hi2, unsigned& lo2) {
    __nv_bfloat16 hx = __float2bfloat16(a.x);
    __nv_bfloat16 hy = __float2bfloat16(a.y);
    __nv_bfloat16 lx = __float2bfloat16(a.x - __bfloat162float(hx));
    __nv_bfloat16 ly = __float2bfloat16(a.y - __bfloat162float(hy));
    __nv_bfloat162 h = __halves2bfloat162(hx, hy);
    __nv_bfloat162 l = __halves2bfloat162(lx, ly);
    hi2 = *reinterpret_cast<unsigned*>(&h);
    lo2 = *reinterpret_cast<unsigned*>(&l);
}

__global__ void k_split_w(const float* __restrict__ src,
                          __nv_bfloat16* __restrict__ whi,
                          __nv_bfloat16* __restrict__ wlo, int n) {
    int i2 = blockIdx.x * blockDim.x + threadIdx.x;
    int total2 = n * (DIM / 2);
    if (i2 >= total2) return;
    float2 a = reinterpret_cast<const float2*>(src)[i2];
    unsigned hi2, lo2;
    split2(a, hi2, lo2);
    reinterpret_cast<unsigned*>(whi)[i2] = hi2;
    reinterpret_cast<unsigned*>(wlo)[i2] = lo2;
}

// ---------------------------------------------------------------------------
// gather aggregation (fused self-loop + bias + relu)
// feature-tiled: one launch covers columns [colOff, colOff+256); 64 threads,
// each thread owns one float4. Keeps the touched h-stripe (51 MB) L2-resident.
// ---------------------------------------------------------------------------
__global__ void __launch_bounds__(64) k_gather(const float* __restrict__ h,
                                               float* __restrict__ agg,
                                               const float* __restrict__ bias,
                                               int colOff) {
    const int node = blockIdx.x;
    const int t    = threadIdx.x;
    const int beg  = g_off[node];
    const int end  = g_off[node + 1];
    const float* hc = h + colOff;

    float4 acc = make_float4(0.f, 0.f, 0.f, 0.f);

    int p = beg;
    for (; p + 4 <= end; p += 4) {
        int   s0 = __ldg(&g_csr_src[p]),     s1 = __ldg(&g_csr_src[p + 1]);
        int   s2 = __ldg(&g_csr_src[p + 2]), s3 = __ldg(&g_csr_src[p + 3]);
        float c0 = __ldg(&g_csr_coef[p]),     c1 = __ldg(&g_csr_coef[p + 1]);
        float c2 = __ldg(&g_csr_coef[p + 2]), c3 = __ldg(&g_csr_coef[p + 3]);
        float4 v0 = reinterpret_cast<const float4*>(hc + (size_t)s0 * DIM)[t];
        float4 v1 = reinterpret_cast<const float4*>(hc + (size_t)s1 * DIM)[t];
        float4 v2 = reinterpret_cast<const float4*>(hc + (size_t)s2 * DIM)[t];
        float4 v3 = reinterpret_cast<const float4*>(hc + (size_t)s3 * DIM)[t];
        acc.x = fmaf(c0, v0.x, acc.x); acc.y = fmaf(c0, v0.y, acc.y);
        acc.z = fmaf(c0, v0.z, acc.z); acc.w = fmaf(c0, v0.w, acc.w);
        acc.x = fmaf(c1, v1.x, acc.x); acc.y = fmaf(c1, v1.y, acc.y);
        acc.z = fmaf(c1, v1.z, acc.z); acc.w = fmaf(c1, v1.w, acc.w);
        acc.x = fmaf(c2, v2.x, acc.x); acc.y = fmaf(c2, v2.y, acc.y);
        acc.z = fmaf(c2, v2.z, acc.z); acc.w = fmaf(c2, v2.w, acc.w);
        acc.x = fmaf(c3, v3.x, acc.x); acc.y = fmaf(c3, v3.y, acc.y);
        acc.z = fmaf(c3, v3.z, acc.z); acc.w = fmaf(c3, v3.w, acc.w);
    }
    for (; p < end; p++) {
        int   src = g_csr_src[p];
        float c   = g_csr_coef[p];
        float4 v  = reinterpret_cast<const float4*>(hc + (size_t)src * DIM)[t];
        acc.x = fmaf(c, v.x, acc.x);
        acc.y = fmaf(c, v.y, acc.y);
        acc.z = fmaf(c, v.z, acc.z);
        acc.w = fmaf(c, v.w, acc.w);
    }

    float cs = g_norm[node];
    cs = cs * cs;
    float4 hv = reinterpret_cast<const float4*>(hc + (size_t)node * DIM)[t];
    float4 b  = reinterpret_cast<const float4*>(bias + colOff)[t];
    float4 r;
    r.x = fmaxf(fmaf(cs, hv.x, acc.x) + b.x, 0.f);
    r.y = fmaxf(fmaf(cs, hv.y, acc.y) + b.y, 0.f);
    r.z = fmaxf(fmaf(cs, hv.z, acc.z) + b.z, 0.f);
    r.w = fmaxf(fmaf(cs, hv.w, acc.w) + b.w, 0.f);
    reinterpret_cast<float4*>(agg + (size_t)node * DIM + colOff)[t] = r;
}

// ---------------------------------------------------------------------------
// pipelined fused split + bf16 mma.sync GEMM  (unchanged — protected win)
// ---------------------------------------------------------------------------
#define GBM 128
#define GBN 128
#define GBK 32
#define APITCH 40
#define SEC    10240
#define STAGEB (4 * SEC)
#define SMEMB  (2 * STAGEB)

__device__ __forceinline__ void mma_bf16(float* d, const unsigned* a,
                                         unsigned b0, unsigned b1) {
    asm volatile(
        "mma.sync.aligned.m16n8k16.row.col.f32.bf16.bf16.f32 "
        "{%0,%1,%2,%3}, {%4,%5,%6,%7}, {%8,%9}, {%0,%1,%2,%3};"
        : "+f"(d[0]), "+f"(d[1]), "+f"(d[2]), "+f"(d[3])
        : "r"(a[0]), "r"(a[1]), "r"(a[2]), "r"(a[3]), "r"(b0), "r"(b1));
}

__device__ __forceinline__ void ldmx4(unsigned* r, unsigned addr) {
    asm volatile(
        "ldmatrix.sync.aligned.m8n8.x4.shared.b16 {%0,%1,%2,%3}, [%4];"
        : "=r"(r[0]), "=r"(r[1]), "=r"(r[2]), "=r"(r[3])
        : "r"(addr));
}

__device__ __forceinline__ void cp_async16(uint32_t dst, const void* src) {
    asm volatile("cp.async.cg.shared.global [%0], [%1], 16;" :: "r"(dst), "l"(src) : "memory");
}
#define CP_COMMIT() asm volatile("cp.async.commit_group;" ::: "memory")
#define CP_WAIT0()  asm volatile("cp.async.wait_group 0;"  ::: "memory")

__global__ void __launch_bounds__(256) k_gemm_fused(const float* __restrict__ A,
                                                    const __nv_bfloat16* __restrict__ Whi,
                                                    const __nv_bfloat16* __restrict__ Wlo,
                                                    float* __restrict__ C,
                                                    const float* __restrict__ bias,
                                                    int N, int M) {
    extern __shared__ char smem[];
    uint32_t sb;
    asm("{ .reg .u64 t; cvta.to.shared.u64 t, %1; cvt.u32.u64 %0, t; }" : "=r"(sb) : "l"(smem));

    const int t    = threadIdx.x;
    const int lane = t & 31;
    const int warp = t >> 5;
    const int wm   = warp & 3;
    const int wn   = warp >> 2;
    const int rowBase = blockIdx.y * GBM;
    const int colBase = blockIdx.x * GBN;

    const int lg = lane >> 3;
    const int lr = lane & 7;

#pragma unroll
    for (int i = 0; i < SMEMB / 16 / 256; i++)
        reinterpret_cast<uint4*>(smem)[i * 256 + t] = make_uint4(0, 0, 0, 0);
    __syncthreads();

    float acc[2][8][4];
#pragma unroll
    for (int i = 0; i < 2; i++)
#pragma unroll
        for (int j = 0; j < 8; j++)
#pragma unroll
            for (int q = 0; q < 4; q++) acc[i][j][q] = 0.f;

    // ---- prologue: stage 0 ----
    {
        const int k0 = 0;
        float4 aPre[4];
#pragma unroll
        for (int L = 0; L < 4; L++) {
            int chunk = t + L * 256;
            int r = chunk >> 3, c = chunk & 7;
            int gr = rowBase + r;
            if (gr < N) aPre[L] = *reinterpret_cast<const float4*>(A + (size_t)gr * DIM + k0 + c * 4);
        }
#pragma unroll
        for (int L = 0; L < 2; L++) {
            int chunk = t + L * 256;
            int r = chunk >> 2, c = chunk & 3;
            int gc = colBase + r;
            if (gc < M) {
                uint32_t off = (uint32_t)((r * APITCH + c * 8) * 2);
                cp_async16(sb + 2 * SEC + off, Whi + (size_t)gc * DIM + k0 + c * 8);
                cp_async16(sb + 3 * SEC + off, Wlo + (size_t)gc * DIM + k0 + c * 8);
            }
        }
        CP_COMMIT();
#pragma unroll
        for (int L = 0; L < 4; L++) {
            int chunk = t + L * 256;
            int r = chunk >> 3, c = chunk & 7;
            int gr = rowBase + r;
            if (gr < N) {
                unsigned h0, l0, h1, l1;
                split2(make_float2(aPre[L].x, aPre[L].y), h0, l0);
                split2(make_float2(aPre[L].z, aPre[L].w), h1, l1);
                uint32_t off = (uint32_t)((r * APITCH + c * 4) * 2);
                *reinterpret_cast<uint2*>(smem + off)       = make_uint2(h0, h1);
                *reinterpret_cast<uint2*>(smem + SEC + off) = make_uint2(l0, l1);
            }
        }
        CP_WAIT0();
        __syncthreads();
    }

    const int NITER = DIM / GBK;   // 16
    for (int it = 0; it < NITER; it++) {
        const int p    = it & 1;
        const bool pre = (it + 1 < NITER);
        const uint32_t cur = sb + (uint32_t)p * STAGEB;
        const uint32_t nxt = sb + (uint32_t)(p ^ 1) * STAGEB;

        float4 aPre[4];
        if (pre) {
            const int k1 = (it + 1) * GBK;
#pragma unroll
            for (int L = 0; L < 4; L++) {
                int chunk = t + L * 256;
                int r = chunk >> 3, c = chunk & 7;
                int gr = rowBase + r;
                if (gr < N) aPre[L] = *reinterpret_cast<const float4*>(A + (size_t)gr * DIM + k1 + c * 4);
            }
#pragma unroll
            for (int L = 0; L < 2; L++) {
                int chunk = t + L * 256;
                int r = chunk >> 2, c = chunk & 3;
                int gc = colBase + r;
                if (gc < M) {
                    uint32_t off = (uint32_t)((r * APITCH + c * 8) * 2);
                    cp_async16(nxt + 2 * SEC + off, Whi + (size_t)gc * DIM + k1 + c * 8);
                    cp_async16(nxt + 3 * SEC + off, Wlo + (size_t)gc * DIM + k1 + c * 8);
                }
            }
            CP_COMMIT();
        }

#pragma unroll
        for (int kk = 0; kk < GBK; kk += 16) {
            unsigned ah[2][4], al[2][4];
#pragma unroll
            for (int mt = 0; mt < 2; mt++) {
                int row = wm * 32 + mt * 16 + (lg & 1) * 8 + lr;
                int kel = kk + (lg >> 1) * 8;
                unsigned off = (unsigned)((row * APITCH + kel) * 2);
                ldmx4(ah[mt], cur + off);
                ldmx4(al[mt], cur + SEC + off);
            }
            unsigned b[4][4];
#pragma unroll
            for (int nq = 0; nq < 4; nq++) {
                int nrow = wn * 64 + nq * 16 + (lg >> 1) * 8 + lr;
                int kel  = kk + (lg & 1) * 8;
                ldmx4(b[nq], cur + 2 * SEC + (unsigned)((nrow * APITCH + kel) * 2));
            }
#pragma unroll
            for (int mt = 0; mt < 2; mt++)
#pragma unroll
                for (int nt = 0; nt < 8; nt++) {
                    int nq = nt >> 1, h = (nt & 1) * 2;
                    mma_bf16(acc[mt][nt], ah[mt], b[nq][h], b[nq][h + 1]);
                }
#pragma unroll
            for (int mt = 0; mt < 2; mt++)
#pragma unroll
                for (int nt = 0; nt < 8; nt++) {
                    int nq = nt >> 1, h = (nt & 1) * 2;
                    mma_bf16(acc[mt][nt], al[mt], b[nq][h], b[nq][h + 1]);
                }
#pragma unroll
            for (int nq = 0; nq < 4; nq++) {
                int nrow = wn * 64 + nq * 16 + (lg >> 1) * 8 + lr;
                int kel  = kk + (lg & 1) * 8;
                ldmx4(b[nq], cur + 3 * SEC + (unsigned)((nrow * APITCH + kel) * 2));
            }
#pragma unroll
            for (int mt = 0; mt < 2; mt++)
#pragma unroll
                for (int nt = 0; nt < 8; nt++) {
                    int nq = nt >> 1, h = (nt & 1) * 2;
                    mma_bf16(acc[mt][nt], ah[mt], b[nq][h], b[nq][h + 1]);
                }
        }

        if (pre) {
            char* nxtg = smem + (size_t)(p ^ 1) * STAGEB;
#pragma unroll
            for (int L = 0; L < 4; L++) {
                int chunk = t + L * 256;
                int r = chunk >> 3, c = chunk & 7;
                int gr = rowBase + r;
                if (gr < N) {
                    unsigned h0, l0, h1, l1;
                    split2(make_float2(aPre[L].x, aPre[L].y), h0, l0);
                    split2(make_float2(aPre[L].z, aPre[L].w), h1, l1);
                    uint32_t off = (uint32_t)((r * APITCH + c * 4) * 2);
                    *reinterpret_cast<uint2*>(nxtg + off)       = make_uint2(h0, h1);
                    *reinterpret_cast<uint2*>(nxtg + SEC + off) = make_uint2(l0, l1);
                }
            }
            CP_WAIT0();
        }
        __syncthreads();
    }

    // epilogue
    const int group = lane >> 2;
    const int qt    = lane & 3;
#pragma unroll
    for (int mt = 0; mt < 2; mt++) {
#pragma unroll
        for (int nt = 0; nt < 8; nt++) {
            int row0 = rowBase + wm * 32 + mt * 16 + group;
            int col  = colBase + wn * 64 + nt * 8 + qt * 2;
            float b0v = 0.f, b1v = 0.f;
            if (bias) {
                if (col < M)     b0v = bias[col];
                if (col + 1 < M) b1v = bias[col + 1];
            }
            if (row0 < N) {
                if (col + 1 < M) {
                    float2 v = make_float2(acc[mt][nt][0] + b0v, acc[mt][nt][1] + b1v);
                    *reinterpret_cast<float2*>(C + (size_t)row0 * M + col) = v;
                } else if (col < M) {
                    C[(size_t)row0 * M + col] = acc[mt][nt][0] + b0v;
                }
            }
            int row1 = row0 + 8;
            if (row1 < N) {
                if (col + 1 < M) {
                    float2 v = make_float2(acc[mt][nt][2] + b0v, acc[mt][nt][3] + b1v);
                    *reinterpret_cast<float2*>(C + (size_t)row1 * M + col) = v;
                } else if (col < M) {
                    C[(size_t)row1 * M + col] = acc[mt][nt][2] + b0v;
                }
            }
        }
    }
}

// ---------------------------------------------------------------------------
// launch
// ---------------------------------------------------------------------------
extern "C" void kernel_launch(void* const* d_in, const int* in_sizes, int n_in,
                              void* d_out, int out_size) {
    const float* x  = (const float*)d_in[0];
    const int*   ei = (const int*)  d_in[1];
    const float* W1 = (const float*)d_in[2];
    const float* b1 = (const float*)d_in[3];
    const float* W2 = (const float*)d_in[4];
    const float* b2 = (const float*)d_in[5];
    const float* Wc = (const float*)d_in[6];
    const float* bc = (const float*)d_in[7];
    float* out = (float*)d_out;

    float *hP = nullptr, *aggP = nullptr;
    __nv_bfloat16 *w1hi, *w1lo, *w2hi, *w2lo, *wchi, *wclo;
    cudaGetSymbolAddress((void**)&hP,   g_h);
    cudaGetSymbolAddress((void**)&aggP, g_agg);
    cudaGetSymbolAddress((void**)&w1hi, g_w1hi);
    cudaGetSymbolAddress((void**)&w1lo, g_w1lo);
    cudaGetSymbolAddress((void**)&w2hi, g_w2hi);
    cudaGetSymbolAddress((void**)&w2lo, g_w2lo);
    cudaGetSymbolAddress((void**)&wchi, g_wchi);
    cudaGetSymbolAddress((void**)&wclo, g_wclo);

    cudaFuncSetAttribute(k_gemm_fused, cudaFuncAttributeMaxDynamicSharedMemorySize, SMEMB);

    // ---- CSR build + norms ----
    k_zero_cnt<<<(N_NODES + 255) / 256, 256>>>();
    k_count   <<<(N_EDGES + 255) / 256, 256>>>(ei);
    k_norm    <<<(N_NODES + 255) / 256, 256>>>();
    k_scan1   <<<SCAN_BLOCKS, 256>>>();
    k_scan2   <<<1, 256>>>();
    k_scan3   <<<SCAN_BLOCKS, 256>>>();
    k_fill    <<<(N_EDGES + 255) / 256, 256>>>(ei);

    // ---- weight splits ----
    const int WT2 = DIM * (DIM / 2);
    k_split_w<<<(WT2 + 255) / 256, 256>>>(W1, w1hi, w1lo, DIM);
    k_split_w<<<(WT2 + 255) / 256, 256>>>(W2, w2hi, w2lo, DIM);
    const int WC2 = NCLS * (DIM / 2);
    k_split_w<<<(WC2 + 255) / 256, 256>>>(Wc, wchi, wclo, NCLS);

    dim3 g1((DIM  + GBN - 1) / GBN, (N_NODES + GBM - 1) / GBM);   // (4, 391)
    dim3 g3((NCLS + GBN - 1) / GBN, (N_NODES + GBM - 1) / GBM);   // (1, 391)

    // ---- layer 1 ----
    k_gemm_fused<<<g1, 256, SMEMB>>>(x, w1hi, w1lo, hP, nullptr, N_NODES, DIM);
    k_gather<<<N_NODES, 64>>>(hP, aggP, b1, 0);
    k_gather<<<N_NODES, 64>>>(hP, aggP, b1, 256);

    // ---- layer 2 ----
    k_gemm_fused<<<g1, 256, SMEMB>>>(aggP, w2hi, w2lo, hP, nullptr, N_NODES, DIM);
    k_gather<<<N_NODES, 64>>>(hP, aggP, b2, 0);
    k_gather<<<N_NODES, 64>>>(hP, aggP, b2, 256);

    // ---- classifier ----
    k_gemm_fused<<<g3, 256, SMEMB>>>(aggP, wchi, wclo, out, bc, N_NODES, NCLS);
}

// round 9
// speedup vs baseline: 3.5795x; 1.0117x over previous
#include <cuda_runtime.h>
#include <cuda_bf16.h>
#include <cstdint>

#define N_NODES 50000
#define N_EDGES 500000
#define DIM     512
#define NCLS    100

// ---------------------------------------------------------------------------
// scratch (device globals)
// ---------------------------------------------------------------------------
__device__ float g_h  [(size_t)N_NODES * DIM];
__device__ float g_agg[(size_t)N_NODES * DIM];
__device__ float g_norm[N_NODES];
__device__ int   g_cnt [N_NODES];
__device__ int   g_fill[N_NODES];
__device__ int   g_off [N_NODES + 1];
__device__ int   g_csr_src [N_EDGES];
__device__ float g_csr_coef[N_EDGES];

__device__ __nv_bfloat16 g_w1hi[(size_t)DIM * DIM];
__device__ __nv_bfloat16 g_w1lo[(size_t)DIM * DIM];
__device__ __nv_bfloat16 g_w2hi[(size_t)DIM * DIM];
__device__ __nv_bfloat16 g_w2lo[(size_t)DIM * DIM];
__device__ __nv_bfloat16 g_wchi[(size_t)NCLS * DIM];
__device__ __nv_bfloat16 g_wclo[(size_t)NCLS * DIM];

#define SCAN_BLOCKS 196
__device__ int g_bsum[SCAN_BLOCKS];
__device__ int g_bpre[SCAN_BLOCKS];

// ---------------------------------------------------------------------------
// CSR build
// ---------------------------------------------------------------------------
__global__ void k_zero_cnt() {
    int i = blockIdx.x * blockDim.x + threadIdx.x;
    if (i < N_NODES) { g_cnt[i] = 0; g_fill[i] = 0; }
}

__global__ void k_count(const int* __restrict__ ei) {
    int e = blockIdx.x * blockDim.x + threadIdx.x;
    if (e < N_EDGES) atomicAdd(&g_cnt[ei[N_EDGES + e]], 1);
}

__global__ void k_norm() {
    int i = blockIdx.x * blockDim.x + threadIdx.x;
    if (i < N_NODES) g_norm[i] = rsqrtf(1.0f + (float)g_cnt[i]);
}

__device__ __forceinline__ int block_scan256(int v, int t, int* sh, int* tot) {
    int incl = v;
#pragma unroll
    for (int o = 1; o < 32; o <<= 1) {
        int u = __shfl_up_sync(0xffffffffu, incl, o);
        if ((t & 31) >= o) incl += u;
    }
    if ((t & 31) == 31) sh[t >> 5] = incl;
    __syncthreads();
    if (t < 8) {
        int w = sh[t];
        int iw = w;
#pragma unroll
        for (int o = 1; o < 8; o <<= 1) {
            int u = __shfl_up_sync(0xffu, iw, o);
            if (t >= o) iw += u;
        }
        sh[t] = iw - w;
        if (t == 7) *tot = iw;
    }
    __syncthreads();
    return incl + sh[t >> 5];
}

__global__ void __launch_bounds__(256) k_scan1() {
    __shared__ int sh[8]; __shared__ int tot;
    int i = blockIdx.x * 256 + threadIdx.x;
    int v = (i < N_NODES) ? g_cnt[i] : 0;
    block_scan256(v, threadIdx.x, sh, &tot);
    __syncthreads();
    if (threadIdx.x == 0) g_bsum[blockIdx.x] = tot;
}

__global__ void __launch_bounds__(256) k_scan2() {
    __shared__ int sh[8]; __shared__ int tot;
    int t = threadIdx.x;
    int v = (t < SCAN_BLOCKS) ? g_bsum[t] : 0;
    int incl = block_scan256(v, t, sh, &tot);
    if (t < SCAN_BLOCKS) g_bpre[t] = incl - v;
}

__global__ void __launch_bounds__(256) k_scan3() {
    __shared__ int sh[8]; __shared__ int tot;
    int i = blockIdx.x * 256 + threadIdx.x;
    int v = (i < N_NODES) ? g_cnt[i] : 0;
    int incl = block_scan256(v, threadIdx.x, sh, &tot);
    if (i < N_NODES) g_off[i + 1] = incl + g_bpre[blockIdx.x];
    if (i == 0) g_off[0] = 0;
}

__global__ void k_fill(const int* __restrict__ ei) {
    int e = blockIdx.x * blockDim.x + threadIdx.x;
    if (e >= N_EDGES) return;
    int src = ei[e];
    int dst = ei[N_EDGES + e];
    int pos = g_off[dst] + atomicAdd(&g_fill[dst], 1);
    g_csr_src [pos] = src;
    g_csr_coef[pos] = g_norm[src] * g_norm[dst];
}

// ---------------------------------------------------------------------------
// fp32 -> (hi, lo) bf16 split
// ---------------------------------------------------------------------------
__device__ __forceinline__ void split2(float2 a, unsigned& hi2, unsigned& lo2) {
    __nv_bfloat16 hx = __float2bfloat16(a.x);
    __nv_bfloat16 hy = __float2bfloat16(a.y);
    __nv_bfloat16 lx = __float2bfloat16(a.x - __bfloat162float(hx));
    __nv_bfloat16 ly = __float2bfloat16(a.y - __bfloat162float(hy));
    __nv_bfloat162 h = __halves2bfloat162(hx, hy);
    __nv_bfloat162 l = __halves2bfloat162(lx, ly);
    hi2 = *reinterpret_cast<unsigned*>(&h);
    lo2 = *reinterpret_cast<unsigned*>(&l);
}

__global__ void k_split_w(const float* __restrict__ src,
                          __nv_bfloat16* __restrict__ whi,
                          __nv_bfloat16* __restrict__ wlo, int n) {
    int i2 = blockIdx.x * blockDim.x + threadIdx.x;
    int total2 = n * (DIM / 2);
    if (i2 >= total2) return;
    float2 a = reinterpret_cast<const float2*>(src)[i2];
    unsigned hi2, lo2;
    split2(a, hi2, lo2);
    reinterpret_cast<unsigned*>(whi)[i2] = hi2;
    reinterpret_cast<unsigned*>(wlo)[i2] = lo2;
}

// ---------------------------------------------------------------------------
// gather aggregation (fused self-loop + bias + relu)
// feature-tiled via blockIdx.y: columns [y*256, y*256+256); 64 threads/block
// ---------------------------------------------------------------------------
__global__ void __launch_bounds__(64) k_gather(const float* __restrict__ h,
                                               float* __restrict__ agg,
                                               const float* __restrict__ bias) {
    const int node   = blockIdx.x;
    const int colOff = blockIdx.y * 256;
    const int t      = threadIdx.x;
    const int beg    = g_off[node];
    const int end    = g_off[node + 1];
    const float* hc  = h + colOff;

    float4 acc = make_float4(0.f, 0.f, 0.f, 0.f);

    int p = beg;
    for (; p + 4 <= end; p += 4) {
        int   s0 = __ldg(&g_csr_src[p]),     s1 = __ldg(&g_csr_src[p + 1]);
        int   s2 = __ldg(&g_csr_src[p + 2]), s3 = __ldg(&g_csr_src[p + 3]);
        float c0 = __ldg(&g_csr_coef[p]),     c1 = __ldg(&g_csr_coef[p + 1]);
        float c2 = __ldg(&g_csr_coef[p + 2]), c3 = __ldg(&g_csr_coef[p + 3]);
        float4 v0 = reinterpret_cast<const float4*>(hc + (size_t)s0 * DIM)[t];
        float4 v1 = reinterpret_cast<const float4*>(hc + (size_t)s1 * DIM)[t];
        float4 v2 = reinterpret_cast<const float4*>(hc + (size_t)s2 * DIM)[t];
        float4 v3 = reinterpret_cast<const float4*>(hc + (size_t)s3 * DIM)[t];
        acc.x = fmaf(c0, v0.x, acc.x); acc.y = fmaf(c0, v0.y, acc.y);
        acc.z = fmaf(c0, v0.z, acc.z); acc.w = fmaf(c0, v0.w, acc.w);
        acc.x = fmaf(c1, v1.x, acc.x); acc.y = fmaf(c1, v1.y, acc.y);
        acc.z = fmaf(c1, v1.z, acc.z); acc.w = fmaf(c1, v1.w, acc.w);
        acc.x = fmaf(c2, v2.x, acc.x); acc.y = fmaf(c2, v2.y, acc.y);
        acc.z = fmaf(c2, v2.z, acc.z); acc.w = fmaf(c2, v2.w, acc.w);
        acc.x = fmaf(c3, v3.x, acc.x); acc.y = fmaf(c3, v3.y, acc.y);
        acc.z = fmaf(c3, v3.z, acc.z); acc.w = fmaf(c3, v3.w, acc.w);
    }
    for (; p < end; p++) {
        int   src = g_csr_src[p];
        float c   = g_csr_coef[p];
        float4 v  = reinterpret_cast<const float4*>(hc + (size_t)src * DIM)[t];
        acc.x = fmaf(c, v.x, acc.x);
        acc.y = fmaf(c, v.y, acc.y);
        acc.z = fmaf(c, v.z, acc.z);
        acc.w = fmaf(c, v.w, acc.w);
    }

    float cs = g_norm[node];
    cs = cs * cs;
    float4 hv = reinterpret_cast<const float4*>(hc + (size_t)node * DIM)[t];
    float4 b  = reinterpret_cast<const float4*>(bias + colOff)[t];
    float4 r;
    r.x = fmaxf(fmaf(cs, hv.x, acc.x) + b.x, 0.f);
    r.y = fmaxf(fmaf(cs, hv.y, acc.y) + b.y, 0.f);
    r.z = fmaxf(fmaf(cs, hv.z, acc.z) + b.z, 0.f);
    r.w = fmaxf(fmaf(cs, hv.w, acc.w) + b.w, 0.f);
    reinterpret_cast<float4*>(agg + (size_t)node * DIM + colOff)[t] = r;
}

// ---------------------------------------------------------------------------
// pipelined fused split + bf16 mma.sync GEMM
// block 128x128, K-chunk 32, 256 threads = 8 warps as 2(M) x 4(N):
// warp tile 64 rows x 32 cols -> per 16-K step: 12 ldmatrix / 48 mma (1:4)
// ---------------------------------------------------------------------------
#define GBM 128
#define GBN 128
#define GBK 32
#define APITCH 40
#define SEC    10240
#define STAGEB (4 * SEC)
#define SMEMB  (2 * STAGEB)

__device__ __forceinline__ void mma_bf16(float* d, const unsigned* a,
                                         unsigned b0, unsigned b1) {
    asm volatile(
        "mma.sync.aligned.m16n8k16.row.col.f32.bf16.bf16.f32 "
        "{%0,%1,%2,%3}, {%4,%5,%6,%7}, {%8,%9}, {%0,%1,%2,%3};"
        : "+f"(d[0]), "+f"(d[1]), "+f"(d[2]), "+f"(d[3])
        : "r"(a[0]), "r"(a[1]), "r"(a[2]), "r"(a[3]), "r"(b0), "r"(b1));
}

__device__ __forceinline__ void ldmx4(unsigned* r, unsigned addr) {
    asm volatile(
        "ldmatrix.sync.aligned.m8n8.x4.shared.b16 {%0,%1,%2,%3}, [%4];"
        : "=r"(r[0]), "=r"(r[1]), "=r"(r[2]), "=r"(r[3])
        : "r"(addr));
}

__device__ __forceinline__ void cp_async16(uint32_t dst, const void* src) {
    asm volatile("cp.async.cg.shared.global [%0], [%1], 16;" :: "r"(dst), "l"(src) : "memory");
}
#define CP_COMMIT() asm volatile("cp.async.commit_group;" ::: "memory")
#define CP_WAIT0()  asm volatile("cp.async.wait_group 0;"  ::: "memory")

__global__ void __launch_bounds__(256) k_gemm_fused(const float* __restrict__ A,
                                                    const __nv_bfloat16* __restrict__ Whi,
                                                    const __nv_bfloat16* __restrict__ Wlo,
                                                    float* __restrict__ C,
                                                    const float* __restrict__ bias,
                                                    int N, int M) {
    extern __shared__ char smem[];
    uint32_t sb;
    asm("{ .reg .u64 t; cvta.to.shared.u64 t, %1; cvt.u32.u64 %0, t; }" : "=r"(sb) : "l"(smem));

    const int t    = threadIdx.x;
    const int lane = t & 31;
    const int warp = t >> 5;
    const int wm   = warp & 1;          // 0..1 -> 64-row slab
    const int wn   = warp >> 1;         // 0..3 -> 32-col slab
    const int rowBase = blockIdx.y * GBM;
    const int colBase = blockIdx.x * GBN;

    const int lg = lane >> 3;
    const int lr = lane & 7;

#pragma unroll
    for (int i = 0; i < SMEMB / 16 / 256; i++)
        reinterpret_cast<uint4*>(smem)[i * 256 + t] = make_uint4(0, 0, 0, 0);
    __syncthreads();

    float acc[4][4][4];
#pragma unroll
    for (int i = 0; i < 4; i++)
#pragma unroll
        for (int j = 0; j < 4; j++)
#pragma unroll
            for (int q = 0; q < 4; q++) acc[i][j][q] = 0.f;

    // ---- prologue: stage 0 ----
    {
        const int k0 = 0;
        float4 aPre[4];
#pragma unroll
        for (int L = 0; L < 4; L++) {
            int chunk = t + L * 256;
            int r = chunk >> 3, c = chunk & 7;
            int gr = rowBase + r;
            if (gr < N) aPre[L] = *reinterpret_cast<const float4*>(A + (size_t)gr * DIM + k0 + c * 4);
        }
#pragma unroll
        for (int L = 0; L < 2; L++) {
            int chunk = t + L * 256;
            int r = chunk >> 2, c = chunk & 3;
            int gc = colBase + r;
            if (gc < M) {
                uint32_t off = (uint32_t)((r * APITCH + c * 8) * 2);
                cp_async16(sb + 2 * SEC + off, Whi + (size_t)gc * DIM + k0 + c * 8);
                cp_async16(sb + 3 * SEC + off, Wlo + (size_t)gc * DIM + k0 + c * 8);
            }
        }
        CP_COMMIT();
#pragma unroll
        for (int L = 0; L < 4; L++) {
            int chunk = t + L * 256;
            int r = chunk >> 3, c = chunk & 7;
            int gr = rowBase + r;
            if (gr < N) {
                unsigned h0, l0, h1, l1;
                split2(make_float2(aPre[L].x, aPre[L].y), h0, l0);
                split2(make_float2(aPre[L].z, aPre[L].w), h1, l1);
                uint32_t off = (uint32_t)((r * APITCH + c * 4) * 2);
                *reinterpret_cast<uint2*>(smem + off)       = make_uint2(h0, h1);
                *reinterpret_cast<uint2*>(smem + SEC + off) = make_uint2(l0, l1);
            }
        }
        CP_WAIT0();
        __syncthreads();
    }

    const int NITER = DIM / GBK;   // 16
    for (int it = 0; it < NITER; it++) {
        const int p    = it & 1;
        const bool pre = (it + 1 < NITER);
        const uint32_t cur = sb + (uint32_t)p * STAGEB;
        const uint32_t nxt = sb + (uint32_t)(p ^ 1) * STAGEB;

        float4 aPre[4];
        if (pre) {
            const int k1 = (it + 1) * GBK;
#pragma unroll
            for (int L = 0; L < 4; L++) {
                int chunk = t + L * 256;
                int r = chunk >> 3, c = chunk & 7;
                int gr = rowBase + r;
                if (gr < N) aPre[L] = *reinterpret_cast<const float4*>(A + (size_t)gr * DIM + k1 + c * 4);
            }
#pragma unroll
            for (int L = 0; L < 2; L++) {
                int chunk = t + L * 256;
                int r = chunk >> 2, c = chunk & 3;
                int gc = colBase + r;
                if (gc < M) {
                    uint32_t off = (uint32_t)((r * APITCH + c * 8) * 2);
                    cp_async16(nxt + 2 * SEC + off, Whi + (size_t)gc * DIM + k1 + c * 8);
                    cp_async16(nxt + 3 * SEC + off, Wlo + (size_t)gc * DIM + k1 + c * 8);
                }
            }
            CP_COMMIT();
        }

#pragma unroll
        for (int kk = 0; kk < GBK; kk += 16) {
            unsigned ah[4][4], al[4][4];
#pragma unroll
            for (int mt = 0; mt < 4; mt++) {
                int row = wm * 64 + mt * 16 + (lg & 1) * 8 + lr;
                int kel = kk + (lg >> 1) * 8;
                unsigned off = (unsigned)((row * APITCH + kel) * 2);
                ldmx4(ah[mt], cur + off);
                ldmx4(al[mt], cur + SEC + off);
            }
            unsigned b[2][4];
            // b = Whi : acc += Ahi*Whi, then Alo*Whi
#pragma unroll
            for (int nq = 0; nq < 2; nq++) {
                int nrow = wn * 32 + nq * 16 + (lg >> 1) * 8 + lr;
                int kel  = kk + (lg & 1) * 8;
                ldmx4(b[nq], cur + 2 * SEC + (unsigned)((nrow * APITCH + kel) * 2));
            }
#pragma unroll
            for (int mt = 0; mt < 4; mt++)
#pragma unroll
                for (int nt = 0; nt < 4; nt++) {
                    int nq = nt >> 1, h = (nt & 1) * 2;
                    mma_bf16(acc[mt][nt], ah[mt], b[nq][h], b[nq][h + 1]);
                }
#pragma unroll
            for (int mt = 0; mt < 4; mt++)
#pragma unroll
                for (int nt = 0; nt < 4; nt++) {
                    int nq = nt >> 1, h = (nt & 1) * 2;
                    mma_bf16(acc[mt][nt], al[mt], b[nq][h], b[nq][h + 1]);
                }
            // b = Wlo : acc += Ahi*Wlo
#pragma unroll
            for (int nq = 0; nq < 2; nq++) {
                int nrow = wn * 32 + nq * 16 + (lg >> 1) * 8 + lr;
                int kel  = kk + (lg & 1) * 8;
                ldmx4(b[nq], cur + 3 * SEC + (unsigned)((nrow * APITCH + kel) * 2));
            }
#pragma unroll
            for (int mt = 0; mt < 4; mt++)
#pragma unroll
                for (int nt = 0; nt < 4; nt++) {
                    int nq = nt >> 1, h = (nt & 1) * 2;
                    mma_bf16(acc[mt][nt], ah[mt], b[nq][h], b[nq][h + 1]);
                }
        }

        if (pre) {
            char* nxtg = smem + (size_t)(p ^ 1) * STAGEB;
#pragma unroll
            for (int L = 0; L < 4; L++) {
                int chunk = t + L * 256;
                int r = chunk >> 3, c = chunk & 7;
                int gr = rowBase + r;
                if (gr < N) {
                    unsigned h0, l0, h1, l1;
                    split2(make_float2(aPre[L].x, aPre[L].y), h0, l0);
                    split2(make_float2(aPre[L].z, aPre[L].w), h1, l1);
                    uint32_t off = (uint32_t)((r * APITCH + c * 4) * 2);
                    *reinterpret_cast<uint2*>(nxtg + off)       = make_uint2(h0, h1);
                    *reinterpret_cast<uint2*>(nxtg + SEC + off) = make_uint2(l0, l1);
                }
            }
            CP_WAIT0();
        }
        __syncthreads();
    }

    // epilogue
    const int group = lane >> 2;
    const int qt    = lane & 3;
#pragma unroll
    for (int mt = 0; mt < 4; mt++) {
#pragma unroll
        for (int nt = 0; nt < 4; nt++) {
            int row0 = rowBase + wm * 64 + mt * 16 + group;
            int col  = colBase + wn * 32 + nt * 8 + qt * 2;
            float b0v = 0.f, b1v = 0.f;
            if (bias) {
                if (col < M)     b0v = bias[col];
                if (col + 1 < M) b1v = bias[col + 1];
            }
            if (row0 < N) {
                if (col + 1 < M) {
                    float2 v = make_float2(acc[mt][nt][0] + b0v, acc[mt][nt][1] + b1v);
                    *reinterpret_cast<float2*>(C + (size_t)row0 * M + col) = v;
                } else if (col < M) {
                    C[(size_t)row0 * M + col] = acc[mt][nt][0] + b0v;
                }
            }
            int row1 = row0 + 8;
            if (row1 < N) {
                if (col + 1 < M) {
                    float2 v = make_float2(acc[mt][nt][2] + b0v, acc[mt][nt][3] + b1v);
                    *reinterpret_cast<float2*>(C + (size_t)row1 * M + col) = v;
                } else if (col < M) {
                    C[(size_t)row1 * M + col] = acc[mt][nt][2] + b0v;
                }
            }
        }
    }
}

// ---------------------------------------------------------------------------
// launch
// ---------------------------------------------------------------------------
extern "C" void kernel_launch(void* const* d_in, const int* in_sizes, int n_in,
                              void* d_out, int out_size) {
    const float* x  = (const float*)d_in[0];
    const int*   ei = (const int*)  d_in[1];
    const float* W1 = (const float*)d_in[2];
    const float* b1 = (const float*)d_in[3];
    const float* W2 = (const float*)d_in[4];
    const float* b2 = (const float*)d_in[5];
    const float* Wc = (const float*)d_in[6];
    const float* bc = (const float*)d_in[7];
    float* out = (float*)d_out;

    float *hP = nullptr, *aggP = nullptr;
    __nv_bfloat16 *w1hi, *w1lo, *w2hi, *w2lo, *wchi, *wclo;
    cudaGetSymbolAddress((void**)&hP,   g_h);
    cudaGetSymbolAddress((void**)&aggP, g_agg);
    cudaGetSymbolAddress((void**)&w1hi, g_w1hi);
    cudaGetSymbolAddress((void**)&w1lo, g_w1lo);
    cudaGetSymbolAddress((void**)&w2hi, g_w2hi);
    cudaGetSymbolAddress((void**)&w2lo, g_w2lo);
    cudaGetSymbolAddress((void**)&wchi, g_wchi);
    cudaGetSymbolAddress((void**)&wclo, g_wclo);

    cudaFuncSetAttribute(k_gemm_fused, cudaFuncAttributeMaxDynamicSharedMemorySize, SMEMB);

    // ---- CSR build + norms ----
    k_zero_cnt<<<(N_NODES + 255) / 256, 256>>>();
    k_count   <<<(N_EDGES + 255) / 256, 256>>>(ei);
    k_norm    <<<(N_NODES + 255) / 256, 256>>>();
    k_scan1   <<<SCAN_BLOCKS, 256>>>();
    k_scan2   <<<1, 256>>>();
    k_scan3   <<<SCAN_BLOCKS, 256>>>();
    k_fill    <<<(N_EDGES + 255) / 256, 256>>>(ei);

    // ---- weight splits ----
    const int WT2 = DIM * (DIM / 2);
    k_split_w<<<(WT2 + 255) / 256, 256>>>(W1, w1hi, w1lo, DIM);
    k_split_w<<<(WT2 + 255) / 256, 256>>>(W2, w2hi, w2lo, DIM);
    const int WC2 = NCLS * (DIM / 2);
    k_split_w<<<(WC2 + 255) / 256, 256>>>(Wc, wchi, wclo, NCLS);

    dim3 g1((DIM  + GBN - 1) / GBN, (N_NODES + GBM - 1) / GBM);   // (4, 391)
    dim3 g3((NCLS + GBN - 1) / GBN, (N_NODES + GBM - 1) / GBM);   // (1, 391)
    dim3 gg(N_NODES, 2);

    // ---- layer 1 ----
    k_gemm_fused<<<g1, 256, SMEMB>>>(x, w1hi, w1lo, hP, nullptr, N_NODES, DIM);
    k_gather    <<<gg, 64>>>(hP, aggP, b1);

    // ---- layer 2 ----
    k_gemm_fused<<<g1, 256, SMEMB>>>(aggP, w2hi, w2lo, hP, nullptr, N_NODES, DIM);
    k_gather    <<<gg, 64>>>(hP, aggP, b2);

    // ---- classifier ----
    k_gemm_fused<<<g3, 256, SMEMB>>>(aggP, wchi, wclo, out, bc, N_NODES, NCLS);
}

// round 10
// speedup vs baseline: 3.6583x; 1.0220x over previous
#include <cuda_runtime.h>
#include <cuda_bf16.h>
#include <cstdint>

#define N_NODES 50000
#define N_EDGES 500000
#define DIM     512
#define NCLS    100

// ---------------------------------------------------------------------------
// scratch (device globals)
// ---------------------------------------------------------------------------
__device__ float g_h  [(size_t)N_NODES * DIM];
__device__ float g_agg[(size_t)N_NODES * DIM];
__device__ float g_norm[N_NODES];
__device__ int   g_cnt [N_NODES];
__device__ int   g_fill[N_NODES];
__device__ int   g_off [N_NODES + 1];
__device__ int   g_csr_src [N_EDGES];
__device__ float g_csr_coef[N_EDGES];

__device__ __nv_bfloat16 g_w1hi[(size_t)DIM * DIM];
__device__ __nv_bfloat16 g_w1lo[(size_t)DIM * DIM];
__device__ __nv_bfloat16 g_w2hi[(size_t)DIM * DIM];
__device__ __nv_bfloat16 g_w2lo[(size_t)DIM * DIM];
__device__ __nv_bfloat16 g_wchi[(size_t)NCLS * DIM];
__device__ __nv_bfloat16 g_wclo[(size_t)NCLS * DIM];

#define SCAN_BLOCKS 196
__device__ int g_bsum[SCAN_BLOCKS];
__device__ int g_bpre[SCAN_BLOCKS];

// ---------------------------------------------------------------------------
// CSR build
// ---------------------------------------------------------------------------
__global__ void k_zero_cnt() {
    int i = blockIdx.x * blockDim.x + threadIdx.x;
    if (i < N_NODES) { g_cnt[i] = 0; g_fill[i] = 0; }
}

__global__ void k_count(const int* __restrict__ ei) {
    int e = blockIdx.x * blockDim.x + threadIdx.x;
    if (e < N_EDGES) atomicAdd(&g_cnt[ei[N_EDGES + e]], 1);
}

__global__ void k_norm() {
    int i = blockIdx.x * blockDim.x + threadIdx.x;
    if (i < N_NODES) g_norm[i] = rsqrtf(1.0f + (float)g_cnt[i]);
}

__device__ __forceinline__ int block_scan256(int v, int t, int* sh, int* tot) {
    int incl = v;
#pragma unroll
    for (int o = 1; o < 32; o <<= 1) {
        int u = __shfl_up_sync(0xffffffffu, incl, o);
        if ((t & 31) >= o) incl += u;
    }
    if ((t & 31) == 31) sh[t >> 5] = incl;
    __syncthreads();
    if (t < 8) {
        int w = sh[t];
        int iw = w;
#pragma unroll
        for (int o = 1; o < 8; o <<= 1) {
            int u = __shfl_up_sync(0xffu, iw, o);
            if (t >= o) iw += u;
        }
        sh[t] = iw - w;
        if (t == 7) *tot = iw;
    }
    __syncthreads();
    return incl + sh[t >> 5];
}

__global__ void __launch_bounds__(256) k_scan1() {
    __shared__ int sh[8]; __shared__ int tot;
    int i = blockIdx.x * 256 + threadIdx.x;
    int v = (i < N_NODES) ? g_cnt[i] : 0;
    block_scan256(v, threadIdx.x, sh, &tot);
    __syncthreads();
    if (threadIdx.x == 0) g_bsum[blockIdx.x] = tot;
}

__global__ void __launch_bounds__(256) k_scan2() {
    __shared__ int sh[8]; __shared__ int tot;
    int t = threadIdx.x;
    int v = (t < SCAN_BLOCKS) ? g_bsum[t] : 0;
    int incl = block_scan256(v, t, sh, &tot);
    if (t < SCAN_BLOCKS) g_bpre[t] = incl - v;
}

__global__ void __launch_bounds__(256) k_scan3() {
    __shared__ int sh[8]; __shared__ int tot;
    int i = blockIdx.x * 256 + threadIdx.x;
    int v = (i < N_NODES) ? g_cnt[i] : 0;
    int incl = block_scan256(v, threadIdx.x, sh, &tot);
    if (i < N_NODES) g_off[i + 1] = incl + g_bpre[blockIdx.x];
    if (i == 0) g_off[0] = 0;
}

__global__ void k_fill(const int* __restrict__ ei) {
    int e = blockIdx.x * blockDim.x + threadIdx.x;
    if (e >= N_EDGES) return;
    int src = ei[e];
    int dst = ei[N_EDGES + e];
    int pos = g_off[dst] + atomicAdd(&g_fill[dst], 1);
    g_csr_src [pos] = src;
    g_csr_coef[pos] = g_norm[src] * g_norm[dst];
}

// ---------------------------------------------------------------------------
// fp32 -> (hi, lo) bf16 split
// ---------------------------------------------------------------------------
__device__ __forceinline__ void split2(float2 a, unsigned& hi2, unsigned& lo2) {
    __nv_bfloat16 hx = __float2bfloat16(a.x);
    __nv_bfloat16 hy = __float2bfloat16(a.y);
    __nv_bfloat16 lx = __float2bfloat16(a.x - __bfloat162float(hx));
    __nv_bfloat16 ly = __float2bfloat16(a.y - __bfloat162float(hy));
    __nv_bfloat162 h = __halves2bfloat162(hx, hy);
    __nv_bfloat162 l = __halves2bfloat162(lx, ly);
    hi2 = *reinterpret_cast<unsigned*>(&h);
    lo2 = *reinterpret_cast<unsigned*>(&l);
}

__global__ void k_split_w(const float* __restrict__ src,
                          __nv_bfloat16* __restrict__ whi,
                          __nv_bfloat16* __restrict__ wlo, int n) {
    int i2 = blockIdx.x * blockDim.x + threadIdx.x;
    int total2 = n * (DIM / 2);
    if (i2 >= total2) return;
    float2 a = reinterpret_cast<const float2*>(src)[i2];
    unsigned hi2, lo2;
    split2(a, hi2, lo2);
    reinterpret_cast<unsigned*>(whi)[i2] = hi2;
    reinterpret_cast<unsigned*>(wlo)[i2] = lo2;
}

// ---------------------------------------------------------------------------
// gather aggregation (fused self-loop + bias + relu)
// feature-tiled via blockIdx.y: columns [y*256, y*256+256); 64 threads/block
// ---------------------------------------------------------------------------
__global__ void __launch_bounds__(64) k_gather(const float* __restrict__ h,
                                               float* __restrict__ agg,
                                               const float* __restrict__ bias) {
    const int node   = blockIdx.x;
    const int colOff = blockIdx.y * 256;
    const int t      = threadIdx.x;
    const int beg    = g_off[node];
    const int end    = g_off[node + 1];
    const float* hc  = h + colOff;

    float4 acc = make_float4(0.f, 0.f, 0.f, 0.f);

    int p = beg;
    for (; p + 4 <= end; p += 4) {
        int   s0 = __ldg(&g_csr_src[p]),     s1 = __ldg(&g_csr_src[p + 1]);
        int   s2 = __ldg(&g_csr_src[p + 2]), s3 = __ldg(&g_csr_src[p + 3]);
        float c0 = __ldg(&g_csr_coef[p]),     c1 = __ldg(&g_csr_coef[p + 1]);
        float c2 = __ldg(&g_csr_coef[p + 2]), c3 = __ldg(&g_csr_coef[p + 3]);
        float4 v0 = reinterpret_cast<const float4*>(hc + (size_t)s0 * DIM)[t];
        float4 v1 = reinterpret_cast<const float4*>(hc + (size_t)s1 * DIM)[t];
        float4 v2 = reinterpret_cast<const float4*>(hc + (size_t)s2 * DIM)[t];
        float4 v3 = reinterpret_cast<const float4*>(hc + (size_t)s3 * DIM)[t];
        acc.x = fmaf(c0, v0.x, acc.x); acc.y = fmaf(c0, v0.y, acc.y);
        acc.z = fmaf(c0, v0.z, acc.z); acc.w = fmaf(c0, v0.w, acc.w);
        acc.x = fmaf(c1, v1.x, acc.x); acc.y = fmaf(c1, v1.y, acc.y);
        acc.z = fmaf(c1, v1.z, acc.z); acc.w = fmaf(c1, v1.w, acc.w);
        acc.x = fmaf(c2, v2.x, acc.x); acc.y = fmaf(c2, v2.y, acc.y);
        acc.z = fmaf(c2, v2.z, acc.z); acc.w = fmaf(c2, v2.w, acc.w);
        acc.x = fmaf(c3, v3.x, acc.x); acc.y = fmaf(c3, v3.y, acc.y);
        acc.z = fmaf(c3, v3.z, acc.z); acc.w = fmaf(c3, v3.w, acc.w);
    }
    for (; p < end; p++) {
        int   src = g_csr_src[p];
        float c   = g_csr_coef[p];
        float4 v  = reinterpret_cast<const float4*>(hc + (size_t)src * DIM)[t];
        acc.x = fmaf(c, v.x, acc.x);
        acc.y = fmaf(c, v.y, acc.y);
        acc.z = fmaf(c, v.z, acc.z);
        acc.w = fmaf(c, v.w, acc.w);
    }

    float cs = g_norm[node];
    cs = cs * cs;
    float4 hv = reinterpret_cast<const float4*>(hc + (size_t)node * DIM)[t];
    float4 b  = reinterpret_cast<const float4*>(bias + colOff)[t];
    float4 r;
    r.x = fmaxf(fmaf(cs, hv.x, acc.x) + b.x, 0.f);
    r.y = fmaxf(fmaf(cs, hv.y, acc.y) + b.y, 0.f);
    r.z = fmaxf(fmaf(cs, hv.z, acc.z) + b.z, 0.f);
    r.w = fmaxf(fmaf(cs, hv.w, acc.w) + b.w, 0.f);
    reinterpret_cast<float4*>(agg + (size_t)node * DIM + colOff)[t] = r;
}

// ---------------------------------------------------------------------------
// pipelined fused split + bf16 mma.sync GEMM (unchanged from R9 — protected)
// block 128x128, K-chunk 32, 256 threads = 8 warps as 2(M) x 4(N)
// ---------------------------------------------------------------------------
#define GBM 128
#define GBN 128
#define GBK 32
#define APITCH 40
#define SEC    10240
#define STAGEB (4 * SEC)
#define SMEMB  (2 * STAGEB)

__device__ __forceinline__ void mma_bf16(float* d, const unsigned* a,
                                         unsigned b0, unsigned b1) {
    asm volatile(
        "mma.sync.aligned.m16n8k16.row.col.f32.bf16.bf16.f32 "
        "{%0,%1,%2,%3}, {%4,%5,%6,%7}, {%8,%9}, {%0,%1,%2,%3};"
        : "+f"(d[0]), "+f"(d[1]), "+f"(d[2]), "+f"(d[3])
        : "r"(a[0]), "r"(a[1]), "r"(a[2]), "r"(a[3]), "r"(b0), "r"(b1));
}

__device__ __forceinline__ void ldmx4(unsigned* r, unsigned addr) {
    asm volatile(
        "ldmatrix.sync.aligned.m8n8.x4.shared.b16 {%0,%1,%2,%3}, [%4];"
        : "=r"(r[0]), "=r"(r[1]), "=r"(r[2]), "=r"(r[3])
        : "r"(addr));
}

__device__ __forceinline__ void cp_async16(uint32_t dst, const void* src) {
    asm volatile("cp.async.cg.shared.global [%0], [%1], 16;" :: "r"(dst), "l"(src) : "memory");
}
#define CP_COMMIT() asm volatile("cp.async.commit_group;" ::: "memory")
#define CP_WAIT0()  asm volatile("cp.async.wait_group 0;"  ::: "memory")

__global__ void __launch_bounds__(256) k_gemm_fused(const float* __restrict__ A,
                                                    const __nv_bfloat16* __restrict__ Whi,
                                                    const __nv_bfloat16* __restrict__ Wlo,
                                                    float* __restrict__ C,
                                                    const float* __restrict__ bias,
                                                    int N, int M) {
    extern __shared__ char smem[];
    uint32_t sb;
    asm("{ .reg .u64 t; cvta.to.shared.u64 t, %1; cvt.u32.u64 %0, t; }" : "=r"(sb) : "l"(smem));

    const int t    = threadIdx.x;
    const int lane = t & 31;
    const int warp = t >> 5;
    const int wm   = warp & 1;
    const int wn   = warp >> 1;
    const int rowBase = blockIdx.y * GBM;
    const int colBase = blockIdx.x * GBN;

    const int lg = lane >> 3;
    const int lr = lane & 7;

#pragma unroll
    for (int i = 0; i < SMEMB / 16 / 256; i++)
        reinterpret_cast<uint4*>(smem)[i * 256 + t] = make_uint4(0, 0, 0, 0);
    __syncthreads();

    float acc[4][4][4];
#pragma unroll
    for (int i = 0; i < 4; i++)
#pragma unroll
        for (int j = 0; j < 4; j++)
#pragma unroll
            for (int q = 0; q < 4; q++) acc[i][j][q] = 0.f;

    // ---- prologue: stage 0 ----
    {
        const int k0 = 0;
        float4 aPre[4];
#pragma unroll
        for (int L = 0; L < 4; L++) {
            int chunk = t + L * 256;
            int r = chunk >> 3, c = chunk & 7;
            int gr = rowBase + r;
            if (gr < N) aPre[L] = *reinterpret_cast<const float4*>(A + (size_t)gr * DIM + k0 + c * 4);
        }
#pragma unroll
        for (int L = 0; L < 2; L++) {
            int chunk = t + L * 256;
            int r = chunk >> 2, c = chunk & 3;
            int gc = colBase + r;
            if (gc < M) {
                uint32_t off = (uint32_t)((r * APITCH + c * 8) * 2);
                cp_async16(sb + 2 * SEC + off, Whi + (size_t)gc * DIM + k0 + c * 8);
                cp_async16(sb + 3 * SEC + off, Wlo + (size_t)gc * DIM + k0 + c * 8);
            }
        }
        CP_COMMIT();
#pragma unroll
        for (int L = 0; L < 4; L++) {
            int chunk = t + L * 256;
            int r = chunk >> 3, c = chunk & 7;
            int gr = rowBase + r;
            if (gr < N) {
                unsigned h0, l0, h1, l1;
                split2(make_float2(aPre[L].x, aPre[L].y), h0, l0);
                split2(make_float2(aPre[L].z, aPre[L].w), h1, l1);
                uint32_t off = (uint32_t)((r * APITCH + c * 4) * 2);
                *reinterpret_cast<uint2*>(smem + off)       = make_uint2(h0, h1);
                *reinterpret_cast<uint2*>(smem + SEC + off) = make_uint2(l0, l1);
            }
        }
        CP_WAIT0();
        __syncthreads();
    }

    const int NITER = DIM / GBK;   // 16
    for (int it = 0; it < NITER; it++) {
        const int p    = it & 1;
        const bool pre = (it + 1 < NITER);
        const uint32_t cur = sb + (uint32_t)p * STAGEB;
        const uint32_t nxt = sb + (uint32_t)(p ^ 1) * STAGEB;

        float4 aPre[4];
        if (pre) {
            const int k1 = (it + 1) * GBK;
#pragma unroll
            for (int L = 0; L < 4; L++) {
                int chunk = t + L * 256;
                int r = chunk >> 3, c = chunk & 7;
                int gr = rowBase + r;
                if (gr < N) aPre[L] = *reinterpret_cast<const float4*>(A + (size_t)gr * DIM + k1 + c * 4);
            }
#pragma unroll
            for (int L = 0; L < 2; L++) {
                int chunk = t + L * 256;
                int r = chunk >> 2, c = chunk & 3;
                int gc = colBase + r;
                if (gc < M) {
                    uint32_t off = (uint32_t)((r * APITCH + c * 8) * 2);
                    cp_async16(nxt + 2 * SEC + off, Whi + (size_t)gc * DIM + k1 + c * 8);
                    cp_async16(nxt + 3 * SEC + off, Wlo + (size_t)gc * DIM + k1 + c * 8);
                }
            }
            CP_COMMIT();
        }

#pragma unroll
        for (int kk = 0; kk < GBK; kk += 16) {
            unsigned ah[4][4], al[4][4];
#pragma unroll
            for (int mt = 0; mt < 4; mt++) {
                int row = wm * 64 + mt * 16 + (lg & 1) * 8 + lr;
                int kel = kk + (lg >> 1) * 8;
                unsigned off = (unsigned)((row * APITCH + kel) * 2);
                ldmx4(ah[mt], cur + off);
                ldmx4(al[mt], cur + SEC + off);
            }
            unsigned b[2][4];
#pragma unroll
            for (int nq = 0; nq < 2; nq++) {
                int nrow = wn * 32 + nq * 16 + (lg >> 1) * 8 + lr;
                int kel  = kk + (lg & 1) * 8;
                ldmx4(b[nq], cur + 2 * SEC + (unsigned)((nrow * APITCH + kel) * 2));
            }
#pragma unroll
            for (int mt = 0; mt < 4; mt++)
#pragma unroll
                for (int nt = 0; nt < 4; nt++) {
                    int nq = nt >> 1, h = (nt & 1) * 2;
                    mma_bf16(acc[mt][nt], ah[mt], b[nq][h], b[nq][h + 1]);
                }
#pragma unroll
            for (int mt = 0; mt < 4; mt++)
#pragma unroll
                for (int nt = 0; nt < 4; nt++) {
                    int nq = nt >> 1, h = (nt & 1) * 2;
                    mma_bf16(acc[mt][nt], al[mt], b[nq][h], b[nq][h + 1]);
                }
#pragma unroll
            for (int nq = 0; nq < 2; nq++) {
                int nrow = wn * 32 + nq * 16 + (lg >> 1) * 8 + lr;
                int kel  = kk + (lg & 1) * 8;
                ldmx4(b[nq], cur + 3 * SEC + (unsigned)((nrow * APITCH + kel) * 2));
            }
#pragma unroll
            for (int mt = 0; mt < 4; mt++)
#pragma unroll
                for (int nt = 0; nt < 4; nt++) {
                    int nq = nt >> 1, h = (nt & 1) * 2;
                    mma_bf16(acc[mt][nt], ah[mt], b[nq][h], b[nq][h + 1]);
                }
        }

        if (pre) {
            char* nxtg = smem + (size_t)(p ^ 1) * STAGEB;
#pragma unroll
            for (int L = 0; L < 4; L++) {
                int chunk = t + L * 256;
                int r = chunk >> 3, c = chunk & 7;
                int gr = rowBase + r;
                if (gr < N) {
                    unsigned h0, l0, h1, l1;
                    split2(make_float2(aPre[L].x, aPre[L].y), h0, l0);
                    split2(make_float2(aPre[L].z, aPre[L].w), h1, l1);
                    uint32_t off = (uint32_t)((r * APITCH + c * 4) * 2);
                    *reinterpret_cast<uint2*>(nxtg + off)       = make_uint2(h0, h1);
                    *reinterpret_cast<uint2*>(nxtg + SEC + off) = make_uint2(l0, l1);
                }
            }
            CP_WAIT0();
        }
        __syncthreads();
    }

    // epilogue
    const int group = lane >> 2;
    const int qt    = lane & 3;
#pragma unroll
    for (int mt = 0; mt < 4; mt++) {
#pragma unroll
        for (int nt = 0; nt < 4; nt++) {
            int row0 = rowBase + wm * 64 + mt * 16 + group;
            int col  = colBase + wn * 32 + nt * 8 + qt * 2;
            float b0v = 0.f, b1v = 0.f;
            if (bias) {
                if (col < M)     b0v = bias[col];
                if (col + 1 < M) b1v = bias[col + 1];
            }
            if (row0 < N) {
                if (col + 1 < M) {
                    float2 v = make_float2(acc[mt][nt][0] + b0v, acc[mt][nt][1] + b1v);
                    *reinterpret_cast<float2*>(C + (size_t)row0 * M + col) = v;
                } else if (col < M) {
                    C[(size_t)row0 * M + col] = acc[mt][nt][0] + b0v;
                }
            }
            int row1 = row0 + 8;
            if (row1 < N) {
                if (col + 1 < M) {
                    float2 v = make_float2(acc[mt][nt][2] + b0v, acc[mt][nt][3] + b1v);
                    *reinterpret_cast<float2*>(C + (size_t)row1 * M + col) = v;
                } else if (col < M) {
                    C[(size_t)row1 * M + col] = acc[mt][nt][2] + b0v;
                }
            }
        }
    }
}

// ---------------------------------------------------------------------------
// launch — capture-fork: CSR chain + W2/Wc splits run concurrently with
// split-W1 + GEMM-1 on a non-blocking side stream; join before gather-1.
// ---------------------------------------------------------------------------
extern "C" void kernel_launch(void* const* d_in, const int* in_sizes, int n_in,
                              void* d_out, int out_size) {
    const float* x  = (const float*)d_in[0];
    const int*   ei = (const int*)  d_in[1];
    const float* W1 = (const float*)d_in[2];
    const float* b1 = (const float*)d_in[3];
    const float* W2 = (const float*)d_in[4];
    const float* b2 = (const float*)d_in[5];
    const float* Wc = (const float*)d_in[6];
    const float* bc = (const float*)d_in[7];
    float* out = (float*)d_out;

    float *hP = nullptr, *aggP = nullptr;
    __nv_bfloat16 *w1hi, *w1lo, *w2hi, *w2lo, *wchi, *wclo;
    cudaGetSymbolAddress((void**)&hP,   g_h);
    cudaGetSymbolAddress((void**)&aggP, g_agg);
    cudaGetSymbolAddress((void**)&w1hi, g_w1hi);
    cudaGetSymbolAddress((void**)&w1lo, g_w1lo);
    cudaGetSymbolAddress((void**)&w2hi, g_w2hi);
    cudaGetSymbolAddress((void**)&w2lo, g_w2lo);
    cudaGetSymbolAddress((void**)&wchi, g_wchi);
    cudaGetSymbolAddress((void**)&wclo, g_wclo);

    cudaFuncSetAttribute(k_gemm_fused, cudaFuncAttributeMaxDynamicSharedMemorySize, SMEMB);

    cudaStream_t s2;
    cudaStreamCreateWithFlags(&s2, cudaStreamNonBlocking);
    cudaEvent_t evFork, evJoin;
    cudaEventCreateWithFlags(&evFork, cudaEventDisableTiming);
    cudaEventCreateWithFlags(&evJoin, cudaEventDisableTiming);

    const int WT2 = DIM * (DIM / 2);
    const int WC2 = NCLS * (DIM / 2);

    // fork: side stream inherits capture from main (legacy) stream
    cudaEventRecord(evFork, 0);
    cudaStreamWaitEvent(s2, evFork, 0);

    // ---- side stream: CSR build + norms + W2/Wc splits ----
    k_zero_cnt<<<(N_NODES + 255) / 256, 256, 0, s2>>>();
    k_count   <<<(N_EDGES + 255) / 256, 256, 0, s2>>>(ei);
    k_norm    <<<(N_NODES + 255) / 256, 256, 0, s2>>>();
    k_scan1   <<<SCAN_BLOCKS, 256, 0, s2>>>();
    k_scan2   <<<1, 256, 0, s2>>>();
    k_scan3   <<<SCAN_BLOCKS, 256, 0, s2>>>();
    k_fill    <<<(N_EDGES + 255) / 256, 256, 0, s2>>>(ei);
    k_split_w <<<(WT2 + 255) / 256, 256, 0, s2>>>(W2, w2hi, w2lo, DIM);
    k_split_w <<<(WC2 + 255) / 256, 256, 0, s2>>>(Wc, wchi, wclo, NCLS);
    cudaEventRecord(evJoin, s2);

    dim3 g1((DIM  + GBN - 1) / GBN, (N_NODES + GBM - 1) / GBM);   // (4, 391)
    dim3 g3((NCLS + GBN - 1) / GBN, (N_NODES + GBM - 1) / GBM);   // (1, 391)
    dim3 gg(N_NODES, 2);

    // ---- main stream: layer 1 GEMM (needs only W1 split) ----
    k_split_w   <<<(WT2 + 255) / 256, 256>>>(W1, w1hi, w1lo, DIM);
    k_gemm_fused<<<g1, 256, SMEMB>>>(x, w1hi, w1lo, hP, nullptr, N_NODES, DIM);

    // join: gather needs CSR; later GEMMs need W2/Wc splits
    cudaStreamWaitEvent(0, evJoin, 0);

    k_gather    <<<gg, 64>>>(hP, aggP, b1);

    // ---- layer 2 ----
    k_gemm_fused<<<g1, 256, SMEMB>>>(aggP, w2hi, w2lo, hP, nullptr, N_NODES, DIM);
    k_gather    <<<gg, 64>>>(hP, aggP, b2);

    // ---- classifier ----
    k_gemm_fused<<<g3, 256, SMEMB>>>(aggP, wchi, wclo, out, bc, N_NODES, NCLS);

    cudaEventDestroy(evFork);
    cudaEventDestroy(evJoin);
    cudaStreamDestroy(s2);
}